// round 12
// baseline (speedup 1.0000x reference)
#include <cuda_runtime.h>
#include <cuda_bf16.h>
#include <cuda_fp16.h>
#include <cstdint>
#include <math.h>

// ===========================================================================
// MarkovBlanketAttention on sm_103 — R9: 3-stage cp.async pipeline with ONE
// __syncthreads per chunk; __launch_bounds__(256,2) to pin 2 CTA/SM.
// Precise chain (Q/K proj, QK^T): packed-bf16x2 2-MMA.
// Fast chain (V proj, PV, out proj): packed-f16-pair single MMA.
// ===========================================================================

namespace {
constexpr int B_   = 2;
constexpr int S_   = 1024;
constexpr int DIN_ = 512;
constexpr int DH_  = 1024;
constexpr int H_   = 16;
constexpr int HD_  = 64;
constexpr int M_   = B_ * S_;
constexpr size_t NTOK = (size_t)M_ * DH_;
constexpr size_t NSC  = (size_t)B_ * H_ * S_ * S_;
}

// ---- scratch (device globals) ----
__device__ uint32_t g_q[3][NTOK];
__device__ uint32_t g_k[3][NTOK];
__device__ float    g_v[3][NTOK];
__device__ uint32_t g_of[3][NTOK / 2];
__device__ float    g_p[3][NTOK];
__device__ float    g_wt[8][DH_ * DH_];
__device__ uint32_t g_wtf[4][DH_ * DH_ / 2];
__device__ uint32_t g_vth[96][HD_ * S_ / 2];
__device__ uint32_t g_ypk[M_ * DIN_];
__device__ uint32_t g_spk[M_ * DH_];
__device__ uint32_t g_bpk[M_ * DH_];
__device__ uint32_t g_zpk[M_ * DH_];
__device__ uint32_t g_sfh[M_ * DH_ / 2];
__device__ uint32_t g_bfh[M_ * DH_ / 2];
__device__ uint32_t g_zfh[M_ * DH_ / 2];

// ---------------------------------------------------------------------------
// helpers
// ---------------------------------------------------------------------------
__device__ __forceinline__ uint32_t smem_u32(const void* p) {
  uint32_t a;
  asm("{ .reg .u64 t; cvta.to.shared.u64 t, %1; cvt.u32.u64 %0, t; }"
      : "=r"(a) : "l"(p));
  return a;
}
__device__ __forceinline__ void cp16(void* smem, const void* g) {
  asm volatile("cp.async.cg.shared.global [%0], [%1], 16;"
               :: "r"(smem_u32(smem)), "l"(g));
}
__device__ __forceinline__ void cp_commit() {
  asm volatile("cp.async.commit_group;" ::: "memory");
}
template <int N>
__device__ __forceinline__ void cp_wait() {
  asm volatile("cp.async.wait_group %0;" :: "n"(N) : "memory");
}
__device__ __forceinline__ void ldsm4(uint32_t* r, uint32_t addr) {
  asm volatile(
      "ldmatrix.sync.aligned.m8n8.x4.shared.b16 {%0,%1,%2,%3}, [%4];"
      : "=r"(r[0]), "=r"(r[1]), "=r"(r[2]), "=r"(r[3]) : "r"(addr));
}
__device__ __forceinline__ void mma_bf16_k16(float* c, const uint32_t* a,
                                             const uint32_t* b) {
  asm volatile(
      "mma.sync.aligned.m16n8k16.row.col.f32.bf16.bf16.f32 "
      "{%0,%1,%2,%3}, {%4,%5,%6,%7}, {%8,%9}, {%0,%1,%2,%3};"
      : "+f"(c[0]), "+f"(c[1]), "+f"(c[2]), "+f"(c[3])
      : "r"(a[0]), "r"(a[1]), "r"(a[2]), "r"(a[3]), "r"(b[0]), "r"(b[1]));
}
__device__ __forceinline__ void mma_f16_k16(float* c, const uint32_t* a,
                                            const uint32_t* b) {
  asm volatile(
      "mma.sync.aligned.m16n8k16.row.col.f32.f16.f16.f32 "
      "{%0,%1,%2,%3}, {%4,%5,%6,%7}, {%8,%9}, {%0,%1,%2,%3};"
      : "+f"(c[0]), "+f"(c[1]), "+f"(c[2]), "+f"(c[3])
      : "r"(a[0]), "r"(a[1]), "r"(a[2]), "r"(a[3]), "r"(b[0]), "r"(b[1]));
}
__device__ __forceinline__ uint32_t pack_bf2(float v) {
  __nv_bfloat16 h = __float2bfloat16_rn(v);
  float fh = __bfloat162float(h);
  __nv_bfloat16 l = __float2bfloat16_rn(v - fh);
  return (uint32_t)__bfloat16_as_ushort(h) |
         ((uint32_t)__bfloat16_as_ushort(l) << 16);
}
__device__ __forceinline__ uint32_t pack_f16p(float a, float b) {
  __half2 h = __floats2half2_rn(a, b);
  return *(uint32_t*)&h;
}

// ---------------------------------------------------------------------------
// GEMM core: 3-stage pipeline, BK=32 words, pitch 36 words (144B rows).
// MODE 0 = fast f16-pair; MODE 1 = precise bf16x2 2-MMA.
// ---------------------------------------------------------------------------
struct Term { const uint32_t* A; const uint32_t* W; const float* bias; };
struct Op   { Term t[3]; float* C; int nt; int K; int lda; int ldb; int ldc; };
struct OpTable { Op op[9]; };

namespace {
constexpr int GBK = 32;
constexpr int GPITCH = 36;
constexpr int GTILE = 128 * GPITCH;        // words per (A or B) tile = 4608
constexpr int STG_W = 2 * GTILE;           // words per stage (A+B) = 9216
constexpr int GEMM_SMEM = 3 * STG_W * 4;   // 110592 B
}

template <int BN, int MODE, bool PACKOUT>
__device__ __forceinline__ void gemm_core(const Op& op, uint32_t* dsm) {
  constexpr int WN = BN / 2;
  constexpr int NT = WN / 8;

  const int t = threadIdx.x;
  const int wid = t >> 5, lane = t & 31;
  const int warp_m = wid & 3;
  const int wn = wid >> 2;
  const int gid = lane >> 2, qid = lane & 3;

  const int bm = blockIdx.y * 128;
  const int bn = blockIdx.x * BN;
  const int cpt = op.K / GBK;
  const int total = op.nt * cpt;

  const uint32_t smb = smem_u32(dsm);
  const uint32_t a_off =
      (((lane & 15) * GPITCH) + ((lane >> 4) << 2)) * 4;
  const uint32_t b_off =
      ((((lane & 7) + ((lane >> 4) << 3)) * GPITCH) + (((lane >> 3) & 1) << 2)) * 4;

  float acc[2][NT][4];
#pragma unroll
  for (int mt = 0; mt < 2; mt++)
#pragma unroll
    for (int nt = 0; nt < NT; nt++)
#pragma unroll
      for (int j = 0; j < 4; j++) acc[mt][nt][j] = 0.f;

  auto load_chunk = [&](int c, int slot) {
    const int term = c / cpt;
    const int k0 = (c - term * cpt) * GBK;
    const uint32_t* __restrict__ A = op.t[term].A;
    const uint32_t* __restrict__ W = op.t[term].W;
    uint32_t* As = dsm + slot * STG_W;
    uint32_t* Bs = As + GTILE;
#pragma unroll
    for (int i = 0; i < 4; i++) {
      int f = t + i * 256;
      int r = f >> 3, c4 = (f & 7) * 4;
      cp16(&As[r * GPITCH + c4], A + (size_t)(bm + r) * op.lda + k0 + c4);
    }
#pragma unroll
    for (int i = 0; i < BN / 32; i++) {
      int f = t + i * 256;
      int r = f >> 3, c4 = (f & 7) * 4;
      cp16(&Bs[r * GPITCH + c4], W + (size_t)(bn + r) * op.ldb + k0 + c4);
    }
  };

  load_chunk(0, 0);
  cp_commit();
  if (total > 1) load_chunk(1, 1);
  cp_commit();

  int slot = 0;
  for (int c = 0; c < total; c++) {
    cp_wait<1>();
    __syncthreads();
    // issue load for c+2 into slot(c+2) = slot(c-1); safe post-sync.
    if (c + 2 < total) {
      int s2 = slot + 2;
      if (s2 >= 3) s2 -= 3;
      load_chunk(c + 2, s2);
    }
    cp_commit();  // always commit (empty groups keep wait-count invariant)

    const uint32_t abase = smb + (uint32_t)(slot * STG_W * 4);
    const uint32_t bbase = abase + (uint32_t)(GTILE * 4);
#pragma unroll
    for (int kk = 0; kk < GBK; kk += 8) {
      uint32_t af[2][4];
#pragma unroll
      for (int mt = 0; mt < 2; mt++) {
        uint32_t ad = abase + a_off +
            (uint32_t)(((warp_m * 32 + mt * 16) * GPITCH + kk) * 4);
        ldsm4(af[mt], ad);
      }
#pragma unroll
      for (int nt2 = 0; nt2 < NT / 2; nt2++) {
        uint32_t bf[4];
        uint32_t bd = bbase + b_off +
            (uint32_t)(((wn * WN + nt2 * 16) * GPITCH + kk) * 4);
        ldsm4(bf, bd);
#pragma unroll
        for (int half = 0; half < 2; half++) {
          const int nt = nt2 * 2 + half;
          uint32_t u0 = bf[half * 2], u1 = bf[half * 2 + 1];
          if (MODE == 1) {
            uint32_t bh[2] = {__byte_perm(u0, 0, 0x1010),
                              __byte_perm(u1, 0, 0x1010)};
            uint32_t bl[2] = {__byte_perm(u0, 0, 0x3232),
                              __byte_perm(u1, 0, 0x3232)};
#pragma unroll
            for (int mt = 0; mt < 2; mt++) {
              mma_bf16_k16(acc[mt][nt], af[mt], bh);
              mma_bf16_k16(acc[mt][nt], af[mt], bl);
            }
          } else {
            uint32_t br[2] = {u0, u1};
#pragma unroll
            for (int mt = 0; mt < 2; mt++) mma_f16_k16(acc[mt][nt], af[mt], br);
          }
        }
      }
    }
    if (++slot == 3) slot = 0;
  }

#pragma unroll
  for (int mt = 0; mt < 2; mt++) {
    int row0 = bm + warp_m * 32 + mt * 16 + gid;
#pragma unroll
    for (int nt = 0; nt < NT; nt++) {
      int col = bn + wn * WN + nt * 8 + qid * 2;
      float b0 = 0.f, b1 = 0.f;
      if (op.t[0].bias) {
        for (int tt = 0; tt < op.nt; tt++) {
          b0 += op.t[tt].bias[col];
          b1 += op.t[tt].bias[col + 1];
        }
      }
      float v00 = acc[mt][nt][0] + b0, v01 = acc[mt][nt][1] + b1;
      float v10 = acc[mt][nt][2] + b0, v11 = acc[mt][nt][3] + b1;
      if (PACKOUT) {
        uint32_t* Cp = (uint32_t*)op.C;
        uint2 p0 = {pack_bf2(v00), pack_bf2(v01)};
        uint2 p1 = {pack_bf2(v10), pack_bf2(v11)};
        *(uint2*)(Cp + (size_t)row0 * op.ldc + col) = p0;
        *(uint2*)(Cp + (size_t)(row0 + 8) * op.ldc + col) = p1;
      } else {
        *(float2*)(op.C + (size_t)row0 * op.ldc + col) = {v00, v01};
        *(float2*)(op.C + (size_t)(row0 + 8) * op.ldc + col) = {v10, v11};
      }
    }
  }
}

__global__ void __launch_bounds__(256, 2) proj_precise(const OpTable tab) {
  extern __shared__ uint32_t ds[];
  gemm_core<128, 1, true>(tab.op[blockIdx.z], ds);
}
__global__ void __launch_bounds__(256, 2) proj_f16(const OpTable tab) {
  extern __shared__ uint32_t ds[];
  gemm_core<128, 0, false>(tab.op[blockIdx.z], ds);
}

// ---------------------------------------------------------------------------
// Fused attention (unchanged from R7/R8).
// ---------------------------------------------------------------------------
namespace {
constexpr int TP = 68;
constexpr int QK_W = 128 * TP;
constexpr int VT_W = 64 * TP;
constexpr int FUSED_SMEM = (3 * QK_W + 2 * VT_W + QK_W) * 4;  // 174080 B
}

__global__ void __launch_bounds__(256) fused_attn(
    const uint32_t* __restrict__ qb, const uint32_t* __restrict__ kb,
    const uint32_t* __restrict__ vtb, const float* __restrict__ bias0,
    const float* __restrict__ bias1, const float* __restrict__ bias2,
    float* __restrict__ score_out, uint32_t* __restrict__ ofb) {
  extern __shared__ uint32_t sm[];
  uint32_t* Qs = sm;
  uint32_t* Ks = sm + QK_W;
  uint32_t* VT = sm + 3 * QK_W;
  uint32_t* Ps = sm + 3 * QK_W + 2 * VT_W;

  const int zz = blockIdx.y;
  const int st = zz >> 5, bh = zz & 31, b = bh >> 4, h = bh & 15;
  const int q0 = blockIdx.x * 128;

  const uint32_t* qp = qb + (size_t)st * NTOK + (size_t)(b * S_ + q0) * DH_ + h * HD_;
  const uint32_t* kp = kb + (size_t)st * NTOK + (size_t)b * S_ * DH_ + h * HD_;
  const uint32_t* vtp = vtb + (size_t)zz * (HD_ * S_ / 2);
  const float* bias = (st == 0) ? bias0 : (st == 1) ? bias1 : bias2;
  const float* brow = bias + (size_t)bh * S_ * S_ + (size_t)q0 * S_;
  float* srow = score_out + (size_t)st * NSC + (size_t)bh * S_ * S_ + (size_t)q0 * S_;
  uint32_t* ofp = ofb + (size_t)st * (NTOK / 2) + (size_t)(b * S_ + q0) * (DH_ / 2) + h * (HD_ / 2);

  const int t = threadIdx.x;
  const int w = t >> 5, lane = t & 31;
  const int gid = lane >> 2, qid = lane & 3;
  const int r0 = w * 16 + gid;

  const uint32_t smb = smem_u32(sm);
  const uint32_t a_off =
      (((lane & 15) * TP) + ((lane >> 4) << 2)) * 4;
  const uint32_t b_off =
      ((((lane & 7) + ((lane >> 4) << 3)) * TP) + (((lane >> 3) & 1) << 2)) * 4;

  auto load_q = [&]() {
#pragma unroll
    for (int i = 0; i < 8; i++) {
      int f = t + i * 256;
      int r = f >> 4, c4 = (f & 15) * 4;
      cp16(&Qs[r * TP + c4], qp + (size_t)r * DH_ + c4);
    }
  };
  auto load_kv = [&](int kbk, int buf) {
#pragma unroll
    for (int i = 0; i < 8; i++) {
      int f = t + i * 256;
      int r = f >> 4, c4 = (f & 15) * 4;
      cp16(&Ks[buf * QK_W + r * TP + c4],
           kp + (size_t)(kbk * 128 + r) * DH_ + c4);
    }
#pragma unroll
    for (int i = 0; i < 4; i++) {
      int f = t + i * 256;
      int r = f >> 4, c4 = (f & 15) * 4;
      cp16(&VT[buf * VT_W + r * TP + c4],
           vtp + (size_t)r * (S_ / 2) + kbk * 64 + c4);
    }
  };

  load_q();
  load_kv(0, 0);
  cp_commit();
  load_kv(1, 1);
  cp_commit();

  float m0 = -1e30f, m1 = -1e30f, l0 = 0.f, l1 = 0.f;
  float oacc[8][4];
#pragma unroll
  for (int j = 0; j < 8; j++)
#pragma unroll
    for (int q = 0; q < 4; q++) oacc[j][q] = 0.f;

  const uint32_t q_base = smb + a_off + (uint32_t)(w * 16 * TP * 4);
  const uint32_t p_base = smb + a_off +
      (uint32_t)((3 * QK_W + 2 * VT_W + w * 16 * TP) * 4);

  for (int it = 0; it < 8; it++) {
    const int buf = it & 1;
    cp_wait<1>();
    __syncthreads();

    float acc[16][4];
#pragma unroll
    for (int nt = 0; nt < 16; nt++)
#pragma unroll
      for (int q = 0; q < 4; q++) acc[nt][q] = 0.f;

#pragma unroll
    for (int kk = 0; kk < 64; kk += 8) {
      uint32_t af[4];
      ldsm4(af, q_base + (uint32_t)(kk * 4));
#pragma unroll
      for (int nt2 = 0; nt2 < 8; nt2++) {
        uint32_t kf[4];
        uint32_t kd = smb + b_off +
            (uint32_t)((QK_W + buf * QK_W + nt2 * 16 * TP + kk) * 4);
        ldsm4(kf, kd);
#pragma unroll
        for (int half = 0; half < 2; half++) {
          const int nt = nt2 * 2 + half;
          uint32_t u0 = kf[half * 2], u1 = kf[half * 2 + 1];
          uint32_t bh2[2] = {__byte_perm(u0, 0, 0x1010), __byte_perm(u1, 0, 0x1010)};
          uint32_t bl2[2] = {__byte_perm(u0, 0, 0x3232), __byte_perm(u1, 0, 0x3232)};
          mma_bf16_k16(acc[nt], af, bh2);
          mma_bf16_k16(acc[nt], af, bl2);
        }
      }
    }

    const int cbase = it * 128;
#pragma unroll
    for (int nt = 0; nt < 16; nt++) {
      int col = cbase + nt * 8 + qid * 2;
      *(float2*)(srow + (size_t)(r0)     * S_ + col) = {acc[nt][0], acc[nt][1]};
      *(float2*)(srow + (size_t)(r0 + 8) * S_ + col) = {acc[nt][2], acc[nt][3]};
      float2 bv0 = *(const float2*)(brow + (size_t)(r0)     * S_ + col);
      float2 bv1 = *(const float2*)(brow + (size_t)(r0 + 8) * S_ + col);
      acc[nt][0] += bv0.x; acc[nt][1] += bv0.y;
      acc[nt][2] += bv1.x; acc[nt][3] += bv1.y;
    }

    float mt0 = -1e30f, mt1 = -1e30f;
#pragma unroll
    for (int nt = 0; nt < 16; nt++) {
      mt0 = fmaxf(mt0, fmaxf(acc[nt][0], acc[nt][1]));
      mt1 = fmaxf(mt1, fmaxf(acc[nt][2], acc[nt][3]));
    }
    mt0 = fmaxf(mt0, __shfl_xor_sync(0xffffffffu, mt0, 1));
    mt0 = fmaxf(mt0, __shfl_xor_sync(0xffffffffu, mt0, 2));
    mt1 = fmaxf(mt1, __shfl_xor_sync(0xffffffffu, mt1, 1));
    mt1 = fmaxf(mt1, __shfl_xor_sync(0xffffffffu, mt1, 2));

    float m0n = fmaxf(m0, mt0), m1n = fmaxf(m1, mt1);
    float sc0 = __expf(m0 - m0n), sc1 = __expf(m1 - m1n);
    m0 = m0n; m1 = m1n;
    l0 *= sc0; l1 *= sc1;
#pragma unroll
    for (int j = 0; j < 8; j++) {
      oacc[j][0] *= sc0; oacc[j][1] *= sc0;
      oacc[j][2] *= sc1; oacc[j][3] *= sc1;
    }

    float ts0 = 0.f, ts1 = 0.f;
#pragma unroll
    for (int nt = 0; nt < 16; nt++) {
      float p00 = __expf(acc[nt][0] - m0);
      float p01 = __expf(acc[nt][1] - m0);
      float p10 = __expf(acc[nt][2] - m1);
      float p11 = __expf(acc[nt][3] - m1);
      ts0 += p00 + p01; ts1 += p10 + p11;
      Ps[(r0)     * TP + nt * 4 + qid] = pack_f16p(p00, p01);
      Ps[(r0 + 8) * TP + nt * 4 + qid] = pack_f16p(p10, p11);
    }
    ts0 += __shfl_xor_sync(0xffffffffu, ts0, 1);
    ts0 += __shfl_xor_sync(0xffffffffu, ts0, 2);
    ts1 += __shfl_xor_sync(0xffffffffu, ts1, 1);
    ts1 += __shfl_xor_sync(0xffffffffu, ts1, 2);
    l0 += ts0; l1 += ts1;
    __syncwarp();

#pragma unroll
    for (int kw = 0; kw < 64; kw += 8) {
      uint32_t ap[4];
      ldsm4(ap, p_base + (uint32_t)(kw * 4));
#pragma unroll
      for (int j2 = 0; j2 < 4; j2++) {
        uint32_t vf[4];
        uint32_t vd = smb + b_off +
            (uint32_t)((3 * QK_W + buf * VT_W + j2 * 16 * TP + kw) * 4);
        ldsm4(vf, vd);
        mma_f16_k16(oacc[j2 * 2],     ap, vf);
        mma_f16_k16(oacc[j2 * 2 + 1], ap, vf + 2);
      }
    }
    __syncthreads();

    if (it + 2 < 8) load_kv(it + 2, buf);
    cp_commit();
  }

  float inv0 = 1.f / l0, inv1 = 1.f / l1;
#pragma unroll
  for (int j = 0; j < 8; j++) {
    int cw = j * 4 + qid;
    ofp[(size_t)(r0)     * (DH_ / 2) + cw] =
        pack_f16p(oacc[j][0] * inv0, oacc[j][1] * inv0);
    ofp[(size_t)(r0 + 8) * (DH_ / 2) + cw] =
        pack_f16p(oacc[j][2] * inv1, oacc[j][3] * inv1);
  }
}

// ---- fused input packing ----
__global__ void __launch_bounds__(256) pack_all(
    const float* __restrict__ y, const float* __restrict__ s,
    const float* __restrict__ b, const float* __restrict__ z,
    uint32_t* __restrict__ ypk, uint32_t* __restrict__ spk,
    uint32_t* __restrict__ bpk, uint32_t* __restrict__ zpk,
    uint32_t* __restrict__ sfh, uint32_t* __restrict__ bfh,
    uint32_t* __restrict__ zfh) {
  const int which = blockIdx.y;
  const int i2 = blockIdx.x * 256 + threadIdx.x;
  const float* src; uint32_t* d_bf; uint32_t* d_fh; int npair;
  switch (which) {
    case 0: src = y; d_bf = ypk; d_fh = nullptr; npair = M_ * DIN_ / 2; break;
    case 1: src = s; d_bf = spk; d_fh = sfh; npair = M_ * DH_ / 2; break;
    case 2: src = b; d_bf = bpk; d_fh = bfh; npair = M_ * DH_ / 2; break;
    default: src = z; d_bf = zpk; d_fh = zfh; npair = M_ * DH_ / 2; break;
  }
  if (i2 >= npair) return;
  float2 v = *(const float2*)(src + 2 * i2);
  d_bf[2 * i2]     = pack_bf2(v.x);
  d_bf[2 * i2 + 1] = pack_bf2(v.y);
  if (d_fh) d_fh[i2] = pack_f16p(v.x, v.y);
}

// ---- weight transpose ----
struct WEnt { const float* src; uint32_t* dst; int K; int pack; };
struct WTab { WEnt e[12]; };

__global__ void __launch_bounds__(256) transpose_w(const WTab tab) {
  WEnt e = tab.e[blockIdx.z];
  int n0 = blockIdx.x * 32, k0 = blockIdx.y * 32;
  if (k0 >= e.K) return;
  __shared__ float tl[32][33];
  int tx = threadIdx.x, ty = threadIdx.y;
#pragma unroll
  for (int i = 0; i < 32; i += 8)
    tl[ty + i][tx] = e.src[(size_t)(k0 + ty + i) * DH_ + n0 + tx];
  __syncthreads();
  if (e.pack == 1) {
#pragma unroll
    for (int i = 0; i < 32; i += 8)
      e.dst[(size_t)(n0 + ty + i) * e.K + k0 + tx] = pack_bf2(tl[tx][ty + i]);
  } else {
    if (tx < 16) {
#pragma unroll
      for (int i = 0; i < 32; i += 8) {
        int nn = ty + i;
        e.dst[(size_t)(n0 + nn) * (e.K / 2) + k0 / 2 + tx] =
            pack_f16p(tl[2 * tx][nn], tl[2 * tx + 1][nn]);
      }
    }
  }
}

// ---- V transpose ----
__global__ void __launch_bounds__(256) transpose_v(const float* __restrict__ v,
                                                   uint32_t* __restrict__ vt) {
  int z = blockIdx.z, st = z >> 5, bh = z & 31, b = bh >> 4, h = bh & 15;
  int c0 = blockIdx.x * 32, k0 = blockIdx.y * 32;
  __shared__ float tl[32][33];
  int tx = threadIdx.x, ty = threadIdx.y;
  const float* src = v + (size_t)st * NTOK + (size_t)b * S_ * DH_ + h * HD_;
  uint32_t* dst = vt + (size_t)z * (HD_ * S_ / 2);
#pragma unroll
  for (int i = 0; i < 32; i += 8)
    tl[ty + i][tx] = src[(size_t)(k0 + ty + i) * DH_ + c0 + tx];
  __syncthreads();
  if (tx < 16) {
#pragma unroll
    for (int i = 0; i < 32; i += 8) {
      int cc = ty + i;
      dst[(size_t)(c0 + cc) * (S_ / 2) + k0 / 2 + tx] =
          pack_f16p(tl[2 * tx][cc], tl[2 * tx + 1][cc]);
    }
  }
}

// ---- residual chain ----
__global__ void __launch_bounds__(256) combine_kernel(
    const float* __restrict__ s, const float* __restrict__ b,
    const float* __restrict__ z, const float* __restrict__ ps,
    const float* __restrict__ pb, const float* __restrict__ pz,
    float* __restrict__ os, float* __restrict__ ob, float* __restrict__ oz) {
  size_t i = (size_t)blockIdx.x * 256 + threadIdx.x;
  if (i >= NTOK) return;
  float so = s[i] + ps[i];
  float bo = so + b[i] + pb[i];
  float zo = bo + z[i] + pz[i];
  os[i] = so; ob[i] = bo; oz[i] = zo;
}

// ===========================================================================
extern "C" void kernel_launch(void* const* d_in, const int* in_sizes, int n_in,
                              void* d_out, int out_size) {
  const float* y    = (const float*)d_in[0];
  const float* s    = (const float*)d_in[1];
  const float* b    = (const float*)d_in[2];
  const float* z    = (const float*)d_in[3];
  const float* ba0  = (const float*)d_in[4];
  const float* ba1  = (const float*)d_in[5];
  const float* ba2  = (const float*)d_in[6];
  const float* W[12] = {
      (const float*)d_in[7],  (const float*)d_in[9],  (const float*)d_in[11],
      (const float*)d_in[13], (const float*)d_in[15], (const float*)d_in[17],
      (const float*)d_in[19], (const float*)d_in[21],
      (const float*)d_in[23], (const float*)d_in[25], (const float*)d_in[27],
      (const float*)d_in[29]};
  const float* C[12] = {
      (const float*)d_in[8],  (const float*)d_in[10], (const float*)d_in[12],
      (const float*)d_in[14], (const float*)d_in[16], (const float*)d_in[18],
      (const float*)d_in[20], (const float*)d_in[22],
      (const float*)d_in[24], (const float*)d_in[26], (const float*)d_in[28],
      (const float*)d_in[30]};
  const int KW[12] = {DIN_, DIN_, DIN_, DH_, DH_, DH_, DH_, DH_,
                      DH_, DH_, DH_, DH_};

  float* out   = (float*)d_out;
  float* s_out = out;
  float* b_out = out + NTOK;
  float* z_out = out + 2 * NTOK;
  float* scb   = out + 3 * NTOK;

  uint32_t *gq, *gk, *gof, *gwtf, *gvth, *gyp, *gsp, *gbp, *gzp, *gsf, *gbf, *gzf;
  float *gv, *gp, *gwt;
  cudaGetSymbolAddress((void**)&gq, g_q);
  cudaGetSymbolAddress((void**)&gk, g_k);
  cudaGetSymbolAddress((void**)&gv, g_v);
  cudaGetSymbolAddress((void**)&gof, g_of);
  cudaGetSymbolAddress((void**)&gp, g_p);
  cudaGetSymbolAddress((void**)&gwt, g_wt);
  cudaGetSymbolAddress((void**)&gwtf, g_wtf);
  cudaGetSymbolAddress((void**)&gvth, g_vth);
  cudaGetSymbolAddress((void**)&gyp, g_ypk);
  cudaGetSymbolAddress((void**)&gsp, g_spk);
  cudaGetSymbolAddress((void**)&gbp, g_bpk);
  cudaGetSymbolAddress((void**)&gzp, g_zpk);
  cudaGetSymbolAddress((void**)&gsf, g_sfh);
  cudaGetSymbolAddress((void**)&gbf, g_bfh);
  cudaGetSymbolAddress((void**)&gzf, g_zfh);

  cudaFuncSetAttribute(fused_attn, cudaFuncAttributeMaxDynamicSharedMemorySize,
                       FUSED_SMEM);
  cudaFuncSetAttribute(proj_precise, cudaFuncAttributeMaxDynamicSharedMemorySize,
                       GEMM_SMEM);
  cudaFuncSetAttribute(proj_f16, cudaFuncAttributeMaxDynamicSharedMemorySize,
                       GEMM_SMEM);

  // --- 1a: pack all inputs ---
  pack_all<<<dim3(4096, 4), 256>>>(y, s, b, z, gyp, gsp, gbp, gzp,
                                   gsf, gbf, gzf);

  // --- 1b: transpose weights ---
  WTab wt{};
  for (int i = 0; i < 8; i++)
    wt.e[i] = {W[i], (uint32_t*)(gwt + (size_t)i * DH_ * DH_), KW[i], 1};
  for (int i = 8; i < 12; i++)
    wt.e[i] = {W[i], gwtf + (size_t)(i - 8) * (DH_ * DH_ / 2), KW[i], 2};
  transpose_w<<<dim3(32, 32, 12), dim3(32, 8)>>>(wt);

  auto WTp = [&](int i) -> const uint32_t* {
    return (const uint32_t*)(gwt + (size_t)i * DH_ * DH_);
  };
  auto WTf = [&](int i) -> const uint32_t* {
    return gwtf + (size_t)(i - 8) * (DH_ * DH_ / 2);
  };

  // --- 2a: Q + K projections (precise) ---
  OpTable tqk{};
  auto setp = [&](int idx, uint32_t* Cp, int K, int nt,
                  const uint32_t* A0, int w0,
                  const uint32_t* A1 = nullptr, int w1 = -1,
                  const uint32_t* A2 = nullptr, int w2 = -1) {
    Op& o = tqk.op[idx];
    o.C = (float*)Cp; o.K = K; o.nt = nt; o.lda = K; o.ldb = K; o.ldc = DH_;
    o.t[0] = {A0, WTp(w0), C[w0]};
    if (nt > 1) o.t[1] = {A1, WTp(w1), C[w1]};
    if (nt > 2) o.t[2] = {A2, WTp(w2), C[w2]};
  };
  setp(0, gq + 0 * NTOK, DIN_, 1, gyp, 0);
  setp(1, gq + 1 * NTOK, DIN_, 1, gyp, 1);
  setp(2, gq + 2 * NTOK, DIN_, 1, gyp, 2);
  setp(3, gk + 0 * NTOK, DH_, 2, gsp, 3, gbp, 4);
  setp(4, gk + 1 * NTOK, DH_, 3, gbp, 6, gsp, 4, gzp, 5);
  setp(5, gk + 2 * NTOK, DH_, 2, gzp, 7, gbp, 5);
  proj_precise<<<dim3(8, 16, 6), 256, GEMM_SMEM>>>(tqk);

  // --- 2b: V projections (f16) ---
  OpTable tv{};
  const uint32_t* fin[3] = {gsf, gbf, gzf};
  for (int i = 0; i < 3; i++) {
    Op& o = tv.op[i];
    o.C = gv + (size_t)i * NTOK; o.K = DH_ / 2; o.nt = 1;
    o.lda = DH_ / 2; o.ldb = DH_ / 2; o.ldc = DH_;
    o.t[0] = {fin[i], WTf(8 + i), C[8 + i]};
  }
  proj_f16<<<dim3(8, 16, 3), 256, GEMM_SMEM>>>(tv);

  // --- 3: V transpose ---
  transpose_v<<<dim3(2, 32, 96), dim3(32, 8)>>>(gv, gvth);

  // --- 4: fused attention ---
  fused_attn<<<dim3(8, 96), 256, FUSED_SMEM>>>(gq, gk, gvth, ba0, ba1, ba2,
                                               scb, gof);

  // --- 5: output projections (f16) ---
  OpTable to{};
  for (int i = 0; i < 3; i++) {
    Op& o = to.op[i];
    o.C = gp + (size_t)i * NTOK; o.K = DH_ / 2; o.nt = 1;
    o.lda = DH_ / 2; o.ldb = DH_ / 2; o.ldc = DH_;
    o.t[0] = {gof + (size_t)i * (NTOK / 2), WTf(11), C[11]};
  }
  proj_f16<<<dim3(8, 16, 3), 256, GEMM_SMEM>>>(to);

  // --- 6: residual chain ---
  combine_kernel<<<(int)((NTOK + 255) / 256), 256>>>(
      s, b, z, gp + 0 * NTOK, gp + 1 * NTOK, gp + 2 * NTOK,
      s_out, b_out, z_out);
}

// round 13
// speedup vs baseline: 1.3683x; 1.3683x over previous
#include <cuda_runtime.h>
#include <cuda_bf16.h>
#include <cuda_fp16.h>
#include <cstdint>
#include <math.h>

// ===========================================================================
// MarkovBlanketAttention on sm_103 — R12: revert to R8 GEMM core (best known),
// merge precise QK-proj + f16 V-proj into ONE mixed-mode launch, heavy ops
// first for tail balancing. No register caps (R9 spill regression lesson).
// ===========================================================================

namespace {
constexpr int B_   = 2;
constexpr int S_   = 1024;
constexpr int DIN_ = 512;
constexpr int DH_  = 1024;
constexpr int H_   = 16;
constexpr int HD_  = 64;
constexpr int M_   = B_ * S_;
constexpr size_t NTOK = (size_t)M_ * DH_;
constexpr size_t NSC  = (size_t)B_ * H_ * S_ * S_;
}

// ---- scratch (device globals) ----
__device__ uint32_t g_q[3][NTOK];
__device__ uint32_t g_k[3][NTOK];
__device__ float    g_v[3][NTOK];
__device__ uint32_t g_of[3][NTOK / 2];
__device__ float    g_p[3][NTOK];
__device__ float    g_wt[8][DH_ * DH_];
__device__ uint32_t g_wtf[4][DH_ * DH_ / 2];
__device__ uint32_t g_vth[96][HD_ * S_ / 2];
__device__ uint32_t g_ypk[M_ * DIN_];
__device__ uint32_t g_spk[M_ * DH_];
__device__ uint32_t g_bpk[M_ * DH_];
__device__ uint32_t g_zpk[M_ * DH_];
__device__ uint32_t g_sfh[M_ * DH_ / 2];
__device__ uint32_t g_bfh[M_ * DH_ / 2];
__device__ uint32_t g_zfh[M_ * DH_ / 2];

// ---------------------------------------------------------------------------
// helpers
// ---------------------------------------------------------------------------
__device__ __forceinline__ uint32_t smem_u32(const void* p) {
  uint32_t a;
  asm("{ .reg .u64 t; cvta.to.shared.u64 t, %1; cvt.u32.u64 %0, t; }"
      : "=r"(a) : "l"(p));
  return a;
}
__device__ __forceinline__ void cp16(void* smem, const void* g) {
  asm volatile("cp.async.cg.shared.global [%0], [%1], 16;"
               :: "r"(smem_u32(smem)), "l"(g));
}
__device__ __forceinline__ void cp_commit() {
  asm volatile("cp.async.commit_group;" ::: "memory");
}
template <int N>
__device__ __forceinline__ void cp_wait() {
  asm volatile("cp.async.wait_group %0;" :: "n"(N) : "memory");
}
__device__ __forceinline__ void ldsm4(uint32_t* r, uint32_t addr) {
  asm volatile(
      "ldmatrix.sync.aligned.m8n8.x4.shared.b16 {%0,%1,%2,%3}, [%4];"
      : "=r"(r[0]), "=r"(r[1]), "=r"(r[2]), "=r"(r[3]) : "r"(addr));
}
__device__ __forceinline__ void mma_bf16_k16(float* c, const uint32_t* a,
                                             const uint32_t* b) {
  asm volatile(
      "mma.sync.aligned.m16n8k16.row.col.f32.bf16.bf16.f32 "
      "{%0,%1,%2,%3}, {%4,%5,%6,%7}, {%8,%9}, {%0,%1,%2,%3};"
      : "+f"(c[0]), "+f"(c[1]), "+f"(c[2]), "+f"(c[3])
      : "r"(a[0]), "r"(a[1]), "r"(a[2]), "r"(a[3]), "r"(b[0]), "r"(b[1]));
}
__device__ __forceinline__ void mma_f16_k16(float* c, const uint32_t* a,
                                            const uint32_t* b) {
  asm volatile(
      "mma.sync.aligned.m16n8k16.row.col.f32.f16.f16.f32 "
      "{%0,%1,%2,%3}, {%4,%5,%6,%7}, {%8,%9}, {%0,%1,%2,%3};"
      : "+f"(c[0]), "+f"(c[1]), "+f"(c[2]), "+f"(c[3])
      : "r"(a[0]), "r"(a[1]), "r"(a[2]), "r"(a[3]), "r"(b[0]), "r"(b[1]));
}
__device__ __forceinline__ uint32_t pack_bf2(float v) {
  __nv_bfloat16 h = __float2bfloat16_rn(v);
  float fh = __bfloat162float(h);
  __nv_bfloat16 l = __float2bfloat16_rn(v - fh);
  return (uint32_t)__bfloat16_as_ushort(h) |
         ((uint32_t)__bfloat16_as_ushort(l) << 16);
}
__device__ __forceinline__ uint32_t pack_f16p(float a, float b) {
  __half2 h = __floats2half2_rn(a, b);
  return *(uint32_t*)&h;
}

// ---------------------------------------------------------------------------
// GEMM core (R8 exact): BK=32 words, pitch 36 words, double buffer.
// MODE 0 = fast f16-pair; MODE 1 = precise bf16x2 2-MMA.
// ---------------------------------------------------------------------------
struct Term { const uint32_t* A; const uint32_t* W; const float* bias; };
struct Op   { Term t[3]; float* C; int nt; int K; int lda; int ldb; int ldc;
              int mode; int pad; };
struct OpTable { Op op[9]; };

namespace {
constexpr int GBK = 32;
constexpr int GPITCH = 36;
constexpr int GTILE = 128 * GPITCH;                    // words per buffer
constexpr int GEMM_SMEM = 4 * GTILE * 4;               // 73728 B
}

template <int BN, int MODE, bool PACKOUT>
__device__ __forceinline__ void gemm_core(const Op& op, uint32_t* dsm) {
  constexpr int WN = BN / 2;
  constexpr int NT = WN / 8;
  uint32_t* As = dsm;                  // [2][GTILE]
  uint32_t* Bs = dsm + 2 * GTILE;      // [2][GTILE]

  const int t = threadIdx.x;
  const int wid = t >> 5, lane = t & 31;
  const int warp_m = wid & 3;
  const int wn = wid >> 2;
  const int gid = lane >> 2, qid = lane & 3;

  const int bm = blockIdx.y * 128;
  const int bn = blockIdx.x * BN;
  const int cpt = op.K / GBK;
  const int total = op.nt * cpt;

  const uint32_t asb = smem_u32(As);
  const uint32_t bsb = smem_u32(Bs);
  const uint32_t a_off =
      (((lane & 15) * GPITCH) + ((lane >> 4) << 2)) * 4;
  const uint32_t b_off =
      ((((lane & 7) + ((lane >> 4) << 3)) * GPITCH) + (((lane >> 3) & 1) << 2)) * 4;

  float acc[2][NT][4];
#pragma unroll
  for (int mt = 0; mt < 2; mt++)
#pragma unroll
    for (int nt = 0; nt < NT; nt++)
#pragma unroll
      for (int j = 0; j < 4; j++) acc[mt][nt][j] = 0.f;

  auto load_chunk = [&](int c, int buf) {
    const int term = c / cpt;
    const int k0 = (c - term * cpt) * GBK;
    const uint32_t* __restrict__ A = op.t[term].A;
    const uint32_t* __restrict__ W = op.t[term].W;
#pragma unroll
    for (int i = 0; i < 4; i++) {
      int f = t + i * 256;
      int r = f >> 3, c4 = (f & 7) * 4;
      cp16(&As[buf * GTILE + r * GPITCH + c4],
           A + (size_t)(bm + r) * op.lda + k0 + c4);
    }
#pragma unroll
    for (int i = 0; i < BN / 32; i++) {
      int f = t + i * 256;
      int r = f >> 3, c4 = (f & 7) * 4;
      cp16(&Bs[buf * GTILE + r * GPITCH + c4],
           W + (size_t)(bn + r) * op.ldb + k0 + c4);
    }
  };

  load_chunk(0, 0);
  cp_commit();

  for (int c = 0; c < total; c++) {
    const int buf = c & 1;
    if (c + 1 < total) load_chunk(c + 1, (c + 1) & 1);
    cp_commit();
    cp_wait<1>();
    __syncthreads();

#pragma unroll
    for (int kk = 0; kk < GBK; kk += 8) {
      uint32_t af[2][4];
#pragma unroll
      for (int mt = 0; mt < 2; mt++) {
        uint32_t ad = asb + a_off +
            (uint32_t)((buf * GTILE + (warp_m * 32 + mt * 16) * GPITCH + kk) * 4);
        ldsm4(af[mt], ad);
      }
#pragma unroll
      for (int nt2 = 0; nt2 < NT / 2; nt2++) {
        uint32_t bf[4];
        uint32_t bd = bsb + b_off +
            (uint32_t)((buf * GTILE + (wn * WN + nt2 * 16) * GPITCH + kk) * 4);
        ldsm4(bf, bd);
#pragma unroll
        for (int half = 0; half < 2; half++) {
          const int nt = nt2 * 2 + half;
          uint32_t u0 = bf[half * 2], u1 = bf[half * 2 + 1];
          if (MODE == 1) {
            uint32_t bh[2] = {__byte_perm(u0, 0, 0x1010),
                              __byte_perm(u1, 0, 0x1010)};
            uint32_t bl[2] = {__byte_perm(u0, 0, 0x3232),
                              __byte_perm(u1, 0, 0x3232)};
#pragma unroll
            for (int mt = 0; mt < 2; mt++) {
              mma_bf16_k16(acc[mt][nt], af[mt], bh);
              mma_bf16_k16(acc[mt][nt], af[mt], bl);
            }
          } else {
            uint32_t br[2] = {u0, u1};
#pragma unroll
            for (int mt = 0; mt < 2; mt++) mma_f16_k16(acc[mt][nt], af[mt], br);
          }
        }
      }
    }
    __syncthreads();
  }

#pragma unroll
  for (int mt = 0; mt < 2; mt++) {
    int row0 = bm + warp_m * 32 + mt * 16 + gid;
#pragma unroll
    for (int nt = 0; nt < NT; nt++) {
      int col = bn + wn * WN + nt * 8 + qid * 2;
      float b0 = 0.f, b1 = 0.f;
      if (op.t[0].bias) {
        for (int tt = 0; tt < op.nt; tt++) {
          b0 += op.t[tt].bias[col];
          b1 += op.t[tt].bias[col + 1];
        }
      }
      float v00 = acc[mt][nt][0] + b0, v01 = acc[mt][nt][1] + b1;
      float v10 = acc[mt][nt][2] + b0, v11 = acc[mt][nt][3] + b1;
      if (PACKOUT) {
        uint32_t* Cp = (uint32_t*)op.C;
        uint2 p0 = {pack_bf2(v00), pack_bf2(v01)};
        uint2 p1 = {pack_bf2(v10), pack_bf2(v11)};
        *(uint2*)(Cp + (size_t)row0 * op.ldc + col) = p0;
        *(uint2*)(Cp + (size_t)(row0 + 8) * op.ldc + col) = p1;
      } else {
        *(float2*)(op.C + (size_t)row0 * op.ldc + col) = {v00, v01};
        *(float2*)(op.C + (size_t)(row0 + 8) * op.ldc + col) = {v10, v11};
      }
    }
  }
}

// Mixed-mode projection kernel: per-CTA uniform dispatch on op.mode.
__global__ void __launch_bounds__(256) proj_mixed(const OpTable tab) {
  extern __shared__ uint32_t ds[];
  const Op& op = tab.op[blockIdx.z];
  if (op.mode == 1)
    gemm_core<128, 1, true>(op, ds);
  else
    gemm_core<128, 0, false>(op, ds);
}

// ---------------------------------------------------------------------------
// Fused attention (unchanged from R7/R8).
// ---------------------------------------------------------------------------
namespace {
constexpr int TP = 68;
constexpr int QK_W = 128 * TP;
constexpr int VT_W = 64 * TP;
constexpr int FUSED_SMEM = (3 * QK_W + 2 * VT_W + QK_W) * 4;  // 174080 B
}

__global__ void __launch_bounds__(256) fused_attn(
    const uint32_t* __restrict__ qb, const uint32_t* __restrict__ kb,
    const uint32_t* __restrict__ vtb, const float* __restrict__ bias0,
    const float* __restrict__ bias1, const float* __restrict__ bias2,
    float* __restrict__ score_out, uint32_t* __restrict__ ofb) {
  extern __shared__ uint32_t sm[];
  uint32_t* Qs = sm;
  uint32_t* Ks = sm + QK_W;
  uint32_t* VT = sm + 3 * QK_W;
  uint32_t* Ps = sm + 3 * QK_W + 2 * VT_W;

  const int zz = blockIdx.y;
  const int st = zz >> 5, bh = zz & 31, b = bh >> 4, h = bh & 15;
  const int q0 = blockIdx.x * 128;

  const uint32_t* qp = qb + (size_t)st * NTOK + (size_t)(b * S_ + q0) * DH_ + h * HD_;
  const uint32_t* kp = kb + (size_t)st * NTOK + (size_t)b * S_ * DH_ + h * HD_;
  const uint32_t* vtp = vtb + (size_t)zz * (HD_ * S_ / 2);
  const float* bias = (st == 0) ? bias0 : (st == 1) ? bias1 : bias2;
  const float* brow = bias + (size_t)bh * S_ * S_ + (size_t)q0 * S_;
  float* srow = score_out + (size_t)st * NSC + (size_t)bh * S_ * S_ + (size_t)q0 * S_;
  uint32_t* ofp = ofb + (size_t)st * (NTOK / 2) + (size_t)(b * S_ + q0) * (DH_ / 2) + h * (HD_ / 2);

  const int t = threadIdx.x;
  const int w = t >> 5, lane = t & 31;
  const int gid = lane >> 2, qid = lane & 3;
  const int r0 = w * 16 + gid;

  const uint32_t smb = smem_u32(sm);
  const uint32_t a_off =
      (((lane & 15) * TP) + ((lane >> 4) << 2)) * 4;
  const uint32_t b_off =
      ((((lane & 7) + ((lane >> 4) << 3)) * TP) + (((lane >> 3) & 1) << 2)) * 4;

  auto load_q = [&]() {
#pragma unroll
    for (int i = 0; i < 8; i++) {
      int f = t + i * 256;
      int r = f >> 4, c4 = (f & 15) * 4;
      cp16(&Qs[r * TP + c4], qp + (size_t)r * DH_ + c4);
    }
  };
  auto load_kv = [&](int kbk, int buf) {
#pragma unroll
    for (int i = 0; i < 8; i++) {
      int f = t + i * 256;
      int r = f >> 4, c4 = (f & 15) * 4;
      cp16(&Ks[buf * QK_W + r * TP + c4],
           kp + (size_t)(kbk * 128 + r) * DH_ + c4);
    }
#pragma unroll
    for (int i = 0; i < 4; i++) {
      int f = t + i * 256;
      int r = f >> 4, c4 = (f & 15) * 4;
      cp16(&VT[buf * VT_W + r * TP + c4],
           vtp + (size_t)r * (S_ / 2) + kbk * 64 + c4);
    }
  };

  load_q();
  load_kv(0, 0);
  cp_commit();
  load_kv(1, 1);
  cp_commit();

  float m0 = -1e30f, m1 = -1e30f, l0 = 0.f, l1 = 0.f;
  float oacc[8][4];
#pragma unroll
  for (int j = 0; j < 8; j++)
#pragma unroll
    for (int q = 0; q < 4; q++) oacc[j][q] = 0.f;

  const uint32_t q_base = smb + a_off + (uint32_t)(w * 16 * TP * 4);
  const uint32_t p_base = smb + a_off +
      (uint32_t)((3 * QK_W + 2 * VT_W + w * 16 * TP) * 4);

  for (int it = 0; it < 8; it++) {
    const int buf = it & 1;
    cp_wait<1>();
    __syncthreads();

    float acc[16][4];
#pragma unroll
    for (int nt = 0; nt < 16; nt++)
#pragma unroll
      for (int q = 0; q < 4; q++) acc[nt][q] = 0.f;

#pragma unroll
    for (int kk = 0; kk < 64; kk += 8) {
      uint32_t af[4];
      ldsm4(af, q_base + (uint32_t)(kk * 4));
#pragma unroll
      for (int nt2 = 0; nt2 < 8; nt2++) {
        uint32_t kf[4];
        uint32_t kd = smb + b_off +
            (uint32_t)((QK_W + buf * QK_W + nt2 * 16 * TP + kk) * 4);
        ldsm4(kf, kd);
#pragma unroll
        for (int half = 0; half < 2; half++) {
          const int nt = nt2 * 2 + half;
          uint32_t u0 = kf[half * 2], u1 = kf[half * 2 + 1];
          uint32_t bh2[2] = {__byte_perm(u0, 0, 0x1010), __byte_perm(u1, 0, 0x1010)};
          uint32_t bl2[2] = {__byte_perm(u0, 0, 0x3232), __byte_perm(u1, 0, 0x3232)};
          mma_bf16_k16(acc[nt], af, bh2);
          mma_bf16_k16(acc[nt], af, bl2);
        }
      }
    }

    const int cbase = it * 128;
#pragma unroll
    for (int nt = 0; nt < 16; nt++) {
      int col = cbase + nt * 8 + qid * 2;
      *(float2*)(srow + (size_t)(r0)     * S_ + col) = {acc[nt][0], acc[nt][1]};
      *(float2*)(srow + (size_t)(r0 + 8) * S_ + col) = {acc[nt][2], acc[nt][3]};
      float2 bv0 = *(const float2*)(brow + (size_t)(r0)     * S_ + col);
      float2 bv1 = *(const float2*)(brow + (size_t)(r0 + 8) * S_ + col);
      acc[nt][0] += bv0.x; acc[nt][1] += bv0.y;
      acc[nt][2] += bv1.x; acc[nt][3] += bv1.y;
    }

    float mt0 = -1e30f, mt1 = -1e30f;
#pragma unroll
    for (int nt = 0; nt < 16; nt++) {
      mt0 = fmaxf(mt0, fmaxf(acc[nt][0], acc[nt][1]));
      mt1 = fmaxf(mt1, fmaxf(acc[nt][2], acc[nt][3]));
    }
    mt0 = fmaxf(mt0, __shfl_xor_sync(0xffffffffu, mt0, 1));
    mt0 = fmaxf(mt0, __shfl_xor_sync(0xffffffffu, mt0, 2));
    mt1 = fmaxf(mt1, __shfl_xor_sync(0xffffffffu, mt1, 1));
    mt1 = fmaxf(mt1, __shfl_xor_sync(0xffffffffu, mt1, 2));

    float m0n = fmaxf(m0, mt0), m1n = fmaxf(m1, mt1);
    float sc0 = __expf(m0 - m0n), sc1 = __expf(m1 - m1n);
    m0 = m0n; m1 = m1n;
    l0 *= sc0; l1 *= sc1;
#pragma unroll
    for (int j = 0; j < 8; j++) {
      oacc[j][0] *= sc0; oacc[j][1] *= sc0;
      oacc[j][2] *= sc1; oacc[j][3] *= sc1;
    }

    float ts0 = 0.f, ts1 = 0.f;
#pragma unroll
    for (int nt = 0; nt < 16; nt++) {
      float p00 = __expf(acc[nt][0] - m0);
      float p01 = __expf(acc[nt][1] - m0);
      float p10 = __expf(acc[nt][2] - m1);
      float p11 = __expf(acc[nt][3] - m1);
      ts0 += p00 + p01; ts1 += p10 + p11;
      Ps[(r0)     * TP + nt * 4 + qid] = pack_f16p(p00, p01);
      Ps[(r0 + 8) * TP + nt * 4 + qid] = pack_f16p(p10, p11);
    }
    ts0 += __shfl_xor_sync(0xffffffffu, ts0, 1);
    ts0 += __shfl_xor_sync(0xffffffffu, ts0, 2);
    ts1 += __shfl_xor_sync(0xffffffffu, ts1, 1);
    ts1 += __shfl_xor_sync(0xffffffffu, ts1, 2);
    l0 += ts0; l1 += ts1;
    __syncwarp();

#pragma unroll
    for (int kw = 0; kw < 64; kw += 8) {
      uint32_t ap[4];
      ldsm4(ap, p_base + (uint32_t)(kw * 4));
#pragma unroll
      for (int j2 = 0; j2 < 4; j2++) {
        uint32_t vf[4];
        uint32_t vd = smb + b_off +
            (uint32_t)((3 * QK_W + buf * VT_W + j2 * 16 * TP + kw) * 4);
        ldsm4(vf, vd);
        mma_f16_k16(oacc[j2 * 2],     ap, vf);
        mma_f16_k16(oacc[j2 * 2 + 1], ap, vf + 2);
      }
    }
    __syncthreads();

    if (it + 2 < 8) load_kv(it + 2, buf);
    cp_commit();
  }

  float inv0 = 1.f / l0, inv1 = 1.f / l1;
#pragma unroll
  for (int j = 0; j < 8; j++) {
    int cw = j * 4 + qid;
    ofp[(size_t)(r0)     * (DH_ / 2) + cw] =
        pack_f16p(oacc[j][0] * inv0, oacc[j][1] * inv0);
    ofp[(size_t)(r0 + 8) * (DH_ / 2) + cw] =
        pack_f16p(oacc[j][2] * inv1, oacc[j][3] * inv1);
  }
}

// ---- fused input packing ----
__global__ void __launch_bounds__(256) pack_all(
    const float* __restrict__ y, const float* __restrict__ s,
    const float* __restrict__ b, const float* __restrict__ z,
    uint32_t* __restrict__ ypk, uint32_t* __restrict__ spk,
    uint32_t* __restrict__ bpk, uint32_t* __restrict__ zpk,
    uint32_t* __restrict__ sfh, uint32_t* __restrict__ bfh,
    uint32_t* __restrict__ zfh) {
  const int which = blockIdx.y;
  const int i2 = blockIdx.x * 256 + threadIdx.x;
  const float* src; uint32_t* d_bf; uint32_t* d_fh; int npair;
  switch (which) {
    case 0: src = y; d_bf = ypk; d_fh = nullptr; npair = M_ * DIN_ / 2; break;
    case 1: src = s; d_bf = spk; d_fh = sfh; npair = M_ * DH_ / 2; break;
    case 2: src = b; d_bf = bpk; d_fh = bfh; npair = M_ * DH_ / 2; break;
    default: src = z; d_bf = zpk; d_fh = zfh; npair = M_ * DH_ / 2; break;
  }
  if (i2 >= npair) return;
  float2 v = *(const float2*)(src + 2 * i2);
  d_bf[2 * i2]     = pack_bf2(v.x);
  d_bf[2 * i2 + 1] = pack_bf2(v.y);
  if (d_fh) d_fh[i2] = pack_f16p(v.x, v.y);
}

// ---- weight transpose ----
struct WEnt { const float* src; uint32_t* dst; int K; int pack; };
struct WTab { WEnt e[12]; };

__global__ void __launch_bounds__(256) transpose_w(const WTab tab) {
  WEnt e = tab.e[blockIdx.z];
  int n0 = blockIdx.x * 32, k0 = blockIdx.y * 32;
  if (k0 >= e.K) return;
  __shared__ float tl[32][33];
  int tx = threadIdx.x, ty = threadIdx.y;
#pragma unroll
  for (int i = 0; i < 32; i += 8)
    tl[ty + i][tx] = e.src[(size_t)(k0 + ty + i) * DH_ + n0 + tx];
  __syncthreads();
  if (e.pack == 1) {
#pragma unroll
    for (int i = 0; i < 32; i += 8)
      e.dst[(size_t)(n0 + ty + i) * e.K + k0 + tx] = pack_bf2(tl[tx][ty + i]);
  } else {
    if (tx < 16) {
#pragma unroll
      for (int i = 0; i < 32; i += 8) {
        int nn = ty + i;
        e.dst[(size_t)(n0 + nn) * (e.K / 2) + k0 / 2 + tx] =
            pack_f16p(tl[2 * tx][nn], tl[2 * tx + 1][nn]);
      }
    }
  }
}

// ---- V transpose ----
__global__ void __launch_bounds__(256) transpose_v(const float* __restrict__ v,
                                                   uint32_t* __restrict__ vt) {
  int z = blockIdx.z, st = z >> 5, bh = z & 31, b = bh >> 4, h = bh & 15;
  int c0 = blockIdx.x * 32, k0 = blockIdx.y * 32;
  __shared__ float tl[32][33];
  int tx = threadIdx.x, ty = threadIdx.y;
  const float* src = v + (size_t)st * NTOK + (size_t)b * S_ * DH_ + h * HD_;
  uint32_t* dst = vt + (size_t)z * (HD_ * S_ / 2);
#pragma unroll
  for (int i = 0; i < 32; i += 8)
    tl[ty + i][tx] = src[(size_t)(k0 + ty + i) * DH_ + c0 + tx];
  __syncthreads();
  if (tx < 16) {
#pragma unroll
    for (int i = 0; i < 32; i += 8) {
      int cc = ty + i;
      dst[(size_t)(c0 + cc) * (S_ / 2) + k0 / 2 + tx] =
          pack_f16p(tl[2 * tx][cc], tl[2 * tx + 1][cc]);
    }
  }
}

// ---- residual chain ----
__global__ void __launch_bounds__(256) combine_kernel(
    const float* __restrict__ s, const float* __restrict__ b,
    const float* __restrict__ z, const float* __restrict__ ps,
    const float* __restrict__ pb, const float* __restrict__ pz,
    float* __restrict__ os, float* __restrict__ ob, float* __restrict__ oz) {
  size_t i = (size_t)blockIdx.x * 256 + threadIdx.x;
  if (i >= NTOK) return;
  float so = s[i] + ps[i];
  float bo = so + b[i] + pb[i];
  float zo = bo + z[i] + pz[i];
  os[i] = so; ob[i] = bo; oz[i] = zo;
}

// ===========================================================================
extern "C" void kernel_launch(void* const* d_in, const int* in_sizes, int n_in,
                              void* d_out, int out_size) {
  const float* y    = (const float*)d_in[0];
  const float* s    = (const float*)d_in[1];
  const float* b    = (const float*)d_in[2];
  const float* z    = (const float*)d_in[3];
  const float* ba0  = (const float*)d_in[4];
  const float* ba1  = (const float*)d_in[5];
  const float* ba2  = (const float*)d_in[6];
  const float* W[12] = {
      (const float*)d_in[7],  (const float*)d_in[9],  (const float*)d_in[11],
      (const float*)d_in[13], (const float*)d_in[15], (const float*)d_in[17],
      (const float*)d_in[19], (const float*)d_in[21],
      (const float*)d_in[23], (const float*)d_in[25], (const float*)d_in[27],
      (const float*)d_in[29]};
  const float* C[12] = {
      (const float*)d_in[8],  (const float*)d_in[10], (const float*)d_in[12],
      (const float*)d_in[14], (const float*)d_in[16], (const float*)d_in[18],
      (const float*)d_in[20], (const float*)d_in[22],
      (const float*)d_in[24], (const float*)d_in[26], (const float*)d_in[28],
      (const float*)d_in[30]};
  const int KW[12] = {DIN_, DIN_, DIN_, DH_, DH_, DH_, DH_, DH_,
                      DH_, DH_, DH_, DH_};

  float* out   = (float*)d_out;
  float* s_out = out;
  float* b_out = out + NTOK;
  float* z_out = out + 2 * NTOK;
  float* scb   = out + 3 * NTOK;

  uint32_t *gq, *gk, *gof, *gwtf, *gvth, *gyp, *gsp, *gbp, *gzp, *gsf, *gbf, *gzf;
  float *gv, *gp, *gwt;
  cudaGetSymbolAddress((void**)&gq, g_q);
  cudaGetSymbolAddress((void**)&gk, g_k);
  cudaGetSymbolAddress((void**)&gv, g_v);
  cudaGetSymbolAddress((void**)&gof, g_of);
  cudaGetSymbolAddress((void**)&gp, g_p);
  cudaGetSymbolAddress((void**)&gwt, g_wt);
  cudaGetSymbolAddress((void**)&gwtf, g_wtf);
  cudaGetSymbolAddress((void**)&gvth, g_vth);
  cudaGetSymbolAddress((void**)&gyp, g_ypk);
  cudaGetSymbolAddress((void**)&gsp, g_spk);
  cudaGetSymbolAddress((void**)&gbp, g_bpk);
  cudaGetSymbolAddress((void**)&gzp, g_zpk);
  cudaGetSymbolAddress((void**)&gsf, g_sfh);
  cudaGetSymbolAddress((void**)&gbf, g_bfh);
  cudaGetSymbolAddress((void**)&gzf, g_zfh);

  cudaFuncSetAttribute(fused_attn, cudaFuncAttributeMaxDynamicSharedMemorySize,
                       FUSED_SMEM);
  cudaFuncSetAttribute(proj_mixed, cudaFuncAttributeMaxDynamicSharedMemorySize,
                       GEMM_SMEM);

  // --- 1a: pack all inputs ---
  pack_all<<<dim3(4096, 4), 256>>>(y, s, b, z, gyp, gsp, gbp, gzp,
                                   gsf, gbf, gzf);

  // --- 1b: transpose weights ---
  WTab wt{};
  for (int i = 0; i < 8; i++)
    wt.e[i] = {W[i], (uint32_t*)(gwt + (size_t)i * DH_ * DH_), KW[i], 1};
  for (int i = 8; i < 12; i++)
    wt.e[i] = {W[i], gwtf + (size_t)(i - 8) * (DH_ * DH_ / 2), KW[i], 2};
  transpose_w<<<dim3(32, 32, 12), dim3(32, 8)>>>(wt);

  auto WTp = [&](int i) -> const uint32_t* {
    return (const uint32_t*)(gwt + (size_t)i * DH_ * DH_);
  };
  auto WTf = [&](int i) -> const uint32_t* {
    return gwtf + (size_t)(i - 8) * (DH_ * DH_ / 2);
  };

  // --- 2: ALL 9 projection ops in ONE launch (heavy precise first) ---
  OpTable tab{};
  auto setp = [&](int idx, uint32_t* Cp, int K, int nt,
                  const uint32_t* A0, int w0,
                  const uint32_t* A1 = nullptr, int w1 = -1,
                  const uint32_t* A2 = nullptr, int w2 = -1) {
    Op& o = tab.op[idx];
    o.C = (float*)Cp; o.K = K; o.nt = nt; o.lda = K; o.ldb = K; o.ldc = DH_;
    o.mode = 1;
    o.t[0] = {A0, WTp(w0), C[w0]};
    if (nt > 1) o.t[1] = {A1, WTp(w1), C[w1]};
    if (nt > 2) o.t[2] = {A2, WTp(w2), C[w2]};
  };
  // heavy -> light: 3-term, 2-term, 2-term, then 1-term Q projections
  setp(0, gk + 1 * NTOK, DH_, 3, gbp, 6, gsp, 4, gzp, 5);
  setp(1, gk + 0 * NTOK, DH_, 2, gsp, 3, gbp, 4);
  setp(2, gk + 2 * NTOK, DH_, 2, gzp, 7, gbp, 5);
  setp(3, gq + 0 * NTOK, DIN_, 1, gyp, 0);
  setp(4, gq + 1 * NTOK, DIN_, 1, gyp, 1);
  setp(5, gq + 2 * NTOK, DIN_, 1, gyp, 2);
  // f16 V projections last (shortest)
  const uint32_t* fin[3] = {gsf, gbf, gzf};
  for (int i = 0; i < 3; i++) {
    Op& o = tab.op[6 + i];
    o.C = gv + (size_t)i * NTOK; o.K = DH_ / 2; o.nt = 1;
    o.lda = DH_ / 2; o.ldb = DH_ / 2; o.ldc = DH_;
    o.mode = 0;
    o.t[0] = {fin[i], WTf(8 + i), C[8 + i]};
  }
  proj_mixed<<<dim3(8, 16, 9), 256, GEMM_SMEM>>>(tab);

  // --- 3: V transpose ---
  transpose_v<<<dim3(2, 32, 96), dim3(32, 8)>>>(gv, gvth);

  // --- 4: fused attention ---
  fused_attn<<<dim3(8, 96), 256, FUSED_SMEM>>>(gq, gk, gvth, ba0, ba1, ba2,
                                               scb, gof);

  // --- 5: output projections (f16) ---
  OpTable to{};
  for (int i = 0; i < 3; i++) {
    Op& o = to.op[i];
    o.C = gp + (size_t)i * NTOK; o.K = DH_ / 2; o.nt = 1;
    o.lda = DH_ / 2; o.ldb = DH_ / 2; o.ldc = DH_;
    o.mode = 0;
    o.t[0] = {gof + (size_t)i * (NTOK / 2), WTf(11), C[11]};
  }
  proj_mixed<<<dim3(8, 16, 3), 256, GEMM_SMEM>>>(to);

  // --- 6: residual chain ---
  combine_kernel<<<(int)((NTOK + 255) / 256), 256>>>(
      s, b, z, gp + 0 * NTOK, gp + 1 * NTOK, gp + 2 * NTOK,
      s_out, b_out, z_out);
}

// round 14
// speedup vs baseline: 1.8021x; 1.3170x over previous
#include <cuda_runtime.h>
#include <cuda_bf16.h>
#include <cuda_fp16.h>
#include <cstdint>
#include <math.h>

// ===========================================================================
// MarkovBlanketAttention on sm_103 — R13: Q/K projections switched to packed-
// f16 single MMA (halves their MMA count; legacy-HMMA issue-rate bound).
// Scores GEMM stays bf16x2 2-MMA on bf2-packed Q/K (no error compounding).
// Fast chain (V proj, PV, out proj) f16 as before. R13-winner structure kept.
// ===========================================================================

namespace {
constexpr int B_   = 2;
constexpr int S_   = 1024;
constexpr int DIN_ = 512;
constexpr int DH_  = 1024;
constexpr int H_   = 16;
constexpr int HD_  = 64;
constexpr int M_   = B_ * S_;
constexpr size_t NTOK = (size_t)M_ * DH_;
constexpr size_t NSC  = (size_t)B_ * H_ * S_ * S_;
}

// ---- scratch (device globals) ----
__device__ uint32_t g_q[3][NTOK];             // bf16x2-packed Q (scores input)
__device__ uint32_t g_k[3][NTOK];             // bf16x2-packed K
__device__ float    g_v[3][NTOK];
__device__ uint32_t g_of[3][NTOK / 2];        // attn out, f16 pairs
__device__ float    g_p[3][NTOK];
__device__ uint32_t g_wtf[12][DH_ * DH_ / 2]; // ALL weights^T, f16 pairs
__device__ uint32_t g_vth[96][HD_ * S_ / 2];
__device__ uint32_t g_yfh[M_ * DIN_ / 2];     // f16-pair inputs
__device__ uint32_t g_sfh[M_ * DH_ / 2];
__device__ uint32_t g_bfh[M_ * DH_ / 2];
__device__ uint32_t g_zfh[M_ * DH_ / 2];

// ---------------------------------------------------------------------------
// helpers
// ---------------------------------------------------------------------------
__device__ __forceinline__ uint32_t smem_u32(const void* p) {
  uint32_t a;
  asm("{ .reg .u64 t; cvta.to.shared.u64 t, %1; cvt.u32.u64 %0, t; }"
      : "=r"(a) : "l"(p));
  return a;
}
__device__ __forceinline__ void cp16(void* smem, const void* g) {
  asm volatile("cp.async.cg.shared.global [%0], [%1], 16;"
               :: "r"(smem_u32(smem)), "l"(g));
}
__device__ __forceinline__ void cp_commit() {
  asm volatile("cp.async.commit_group;" ::: "memory");
}
template <int N>
__device__ __forceinline__ void cp_wait() {
  asm volatile("cp.async.wait_group %0;" :: "n"(N) : "memory");
}
__device__ __forceinline__ void ldsm4(uint32_t* r, uint32_t addr) {
  asm volatile(
      "ldmatrix.sync.aligned.m8n8.x4.shared.b16 {%0,%1,%2,%3}, [%4];"
      : "=r"(r[0]), "=r"(r[1]), "=r"(r[2]), "=r"(r[3]) : "r"(addr));
}
__device__ __forceinline__ void mma_bf16_k16(float* c, const uint32_t* a,
                                             const uint32_t* b) {
  asm volatile(
      "mma.sync.aligned.m16n8k16.row.col.f32.bf16.bf16.f32 "
      "{%0,%1,%2,%3}, {%4,%5,%6,%7}, {%8,%9}, {%0,%1,%2,%3};"
      : "+f"(c[0]), "+f"(c[1]), "+f"(c[2]), "+f"(c[3])
      : "r"(a[0]), "r"(a[1]), "r"(a[2]), "r"(a[3]), "r"(b[0]), "r"(b[1]));
}
__device__ __forceinline__ void mma_f16_k16(float* c, const uint32_t* a,
                                            const uint32_t* b) {
  asm volatile(
      "mma.sync.aligned.m16n8k16.row.col.f32.f16.f16.f32 "
      "{%0,%1,%2,%3}, {%4,%5,%6,%7}, {%8,%9}, {%0,%1,%2,%3};"
      : "+f"(c[0]), "+f"(c[1]), "+f"(c[2]), "+f"(c[3])
      : "r"(a[0]), "r"(a[1]), "r"(a[2]), "r"(a[3]), "r"(b[0]), "r"(b[1]));
}
__device__ __forceinline__ uint32_t pack_bf2(float v) {
  __nv_bfloat16 h = __float2bfloat16_rn(v);
  float fh = __bfloat162float(h);
  __nv_bfloat16 l = __float2bfloat16_rn(v - fh);
  return (uint32_t)__bfloat16_as_ushort(h) |
         ((uint32_t)__bfloat16_as_ushort(l) << 16);
}
__device__ __forceinline__ uint32_t pack_f16p(float a, float b) {
  __half2 h = __floats2half2_rn(a, b);
  return *(uint32_t*)&h;
}

// ---------------------------------------------------------------------------
// GEMM core (R8/R13 structure): BK=32 words, pitch 36, double buffer.
// MODE 0 = f16-pair single MMA; MODE 1 = bf16x2 2-MMA (kept for revert).
// ---------------------------------------------------------------------------
struct Term { const uint32_t* A; const uint32_t* W; const float* bias; };
struct Op   { Term t[3]; float* C; int nt; int K; int lda; int ldb; int ldc;
              int mode; int pad; };
struct OpTable { Op op[9]; };

namespace {
constexpr int GBK = 32;
constexpr int GPITCH = 36;
constexpr int GTILE = 128 * GPITCH;
constexpr int GEMM_SMEM = 4 * GTILE * 4;   // 73728 B
}

template <int BN, int MODE, bool PACKOUT>
__device__ __forceinline__ void gemm_core(const Op& op, uint32_t* dsm) {
  constexpr int WN = BN / 2;
  constexpr int NT = WN / 8;
  uint32_t* As = dsm;
  uint32_t* Bs = dsm + 2 * GTILE;

  const int t = threadIdx.x;
  const int wid = t >> 5, lane = t & 31;
  const int warp_m = wid & 3;
  const int wn = wid >> 2;
  const int gid = lane >> 2, qid = lane & 3;

  const int bm = blockIdx.y * 128;
  const int bn = blockIdx.x * BN;
  const int cpt = op.K / GBK;
  const int total = op.nt * cpt;

  const uint32_t asb = smem_u32(As);
  const uint32_t bsb = smem_u32(Bs);
  const uint32_t a_off =
      (((lane & 15) * GPITCH) + ((lane >> 4) << 2)) * 4;
  const uint32_t b_off =
      ((((lane & 7) + ((lane >> 4) << 3)) * GPITCH) + (((lane >> 3) & 1) << 2)) * 4;

  float acc[2][NT][4];
#pragma unroll
  for (int mt = 0; mt < 2; mt++)
#pragma unroll
    for (int nt = 0; nt < NT; nt++)
#pragma unroll
      for (int j = 0; j < 4; j++) acc[mt][nt][j] = 0.f;

  auto load_chunk = [&](int c, int buf) {
    const int term = c / cpt;
    const int k0 = (c - term * cpt) * GBK;
    const uint32_t* __restrict__ A = op.t[term].A;
    const uint32_t* __restrict__ W = op.t[term].W;
#pragma unroll
    for (int i = 0; i < 4; i++) {
      int f = t + i * 256;
      int r = f >> 3, c4 = (f & 7) * 4;
      cp16(&As[buf * GTILE + r * GPITCH + c4],
           A + (size_t)(bm + r) * op.lda + k0 + c4);
    }
#pragma unroll
    for (int i = 0; i < BN / 32; i++) {
      int f = t + i * 256;
      int r = f >> 3, c4 = (f & 7) * 4;
      cp16(&Bs[buf * GTILE + r * GPITCH + c4],
           W + (size_t)(bn + r) * op.ldb + k0 + c4);
    }
  };

  load_chunk(0, 0);
  cp_commit();

  for (int c = 0; c < total; c++) {
    const int buf = c & 1;
    if (c + 1 < total) load_chunk(c + 1, (c + 1) & 1);
    cp_commit();
    cp_wait<1>();
    __syncthreads();

#pragma unroll
    for (int kk = 0; kk < GBK; kk += 8) {
      uint32_t af[2][4];
#pragma unroll
      for (int mt = 0; mt < 2; mt++) {
        uint32_t ad = asb + a_off +
            (uint32_t)((buf * GTILE + (warp_m * 32 + mt * 16) * GPITCH + kk) * 4);
        ldsm4(af[mt], ad);
      }
#pragma unroll
      for (int nt2 = 0; nt2 < NT / 2; nt2++) {
        uint32_t bf[4];
        uint32_t bd = bsb + b_off +
            (uint32_t)((buf * GTILE + (wn * WN + nt2 * 16) * GPITCH + kk) * 4);
        ldsm4(bf, bd);
#pragma unroll
        for (int half = 0; half < 2; half++) {
          const int nt = nt2 * 2 + half;
          uint32_t u0 = bf[half * 2], u1 = bf[half * 2 + 1];
          if (MODE == 1) {
            uint32_t bh[2] = {__byte_perm(u0, 0, 0x1010),
                              __byte_perm(u1, 0, 0x1010)};
            uint32_t bl[2] = {__byte_perm(u0, 0, 0x3232),
                              __byte_perm(u1, 0, 0x3232)};
#pragma unroll
            for (int mt = 0; mt < 2; mt++) {
              mma_bf16_k16(acc[mt][nt], af[mt], bh);
              mma_bf16_k16(acc[mt][nt], af[mt], bl);
            }
          } else {
            uint32_t br[2] = {u0, u1};
#pragma unroll
            for (int mt = 0; mt < 2; mt++) mma_f16_k16(acc[mt][nt], af[mt], br);
          }
        }
      }
    }
    __syncthreads();
  }

#pragma unroll
  for (int mt = 0; mt < 2; mt++) {
    int row0 = bm + warp_m * 32 + mt * 16 + gid;
#pragma unroll
    for (int nt = 0; nt < NT; nt++) {
      int col = bn + wn * WN + nt * 8 + qid * 2;
      float b0 = 0.f, b1 = 0.f;
      if (op.t[0].bias) {
        for (int tt = 0; tt < op.nt; tt++) {
          b0 += op.t[tt].bias[col];
          b1 += op.t[tt].bias[col + 1];
        }
      }
      float v00 = acc[mt][nt][0] + b0, v01 = acc[mt][nt][1] + b1;
      float v10 = acc[mt][nt][2] + b0, v11 = acc[mt][nt][3] + b1;
      if (PACKOUT) {
        uint32_t* Cp = (uint32_t*)op.C;
        uint2 p0 = {pack_bf2(v00), pack_bf2(v01)};
        uint2 p1 = {pack_bf2(v10), pack_bf2(v11)};
        *(uint2*)(Cp + (size_t)row0 * op.ldc + col) = p0;
        *(uint2*)(Cp + (size_t)(row0 + 8) * op.ldc + col) = p1;
      } else {
        *(float2*)(op.C + (size_t)row0 * op.ldc + col) = {v00, v01};
        *(float2*)(op.C + (size_t)(row0 + 8) * op.ldc + col) = {v10, v11};
      }
    }
  }
}

// Mixed-mode projection kernel: per-CTA uniform dispatch on op.mode.
// mode 0: f16 MMA, fp32 out.  mode 2: f16 MMA, bf2-packed out (Q/K).
__global__ void __launch_bounds__(256) proj_mixed(const OpTable tab) {
  extern __shared__ uint32_t ds[];
  const Op& op = tab.op[blockIdx.z];
  if (op.mode == 2)
    gemm_core<128, 0, true>(op, ds);
  else
    gemm_core<128, 0, false>(op, ds);
}

// ---------------------------------------------------------------------------
// Fused attention (unchanged — scores stay bf16x2 2-MMA).
// ---------------------------------------------------------------------------
namespace {
constexpr int TP = 68;
constexpr int QK_W = 128 * TP;
constexpr int VT_W = 64 * TP;
constexpr int FUSED_SMEM = (3 * QK_W + 2 * VT_W + QK_W) * 4;  // 174080 B
}

__global__ void __launch_bounds__(256) fused_attn(
    const uint32_t* __restrict__ qb, const uint32_t* __restrict__ kb,
    const uint32_t* __restrict__ vtb, const float* __restrict__ bias0,
    const float* __restrict__ bias1, const float* __restrict__ bias2,
    float* __restrict__ score_out, uint32_t* __restrict__ ofb) {
  extern __shared__ uint32_t sm[];
  uint32_t* Qs = sm;
  uint32_t* Ks = sm + QK_W;
  uint32_t* VT = sm + 3 * QK_W;
  uint32_t* Ps = sm + 3 * QK_W + 2 * VT_W;

  const int zz = blockIdx.y;
  const int st = zz >> 5, bh = zz & 31, b = bh >> 4, h = bh & 15;
  const int q0 = blockIdx.x * 128;

  const uint32_t* qp = qb + (size_t)st * NTOK + (size_t)(b * S_ + q0) * DH_ + h * HD_;
  const uint32_t* kp = kb + (size_t)st * NTOK + (size_t)b * S_ * DH_ + h * HD_;
  const uint32_t* vtp = vtb + (size_t)zz * (HD_ * S_ / 2);
  const float* bias = (st == 0) ? bias0 : (st == 1) ? bias1 : bias2;
  const float* brow = bias + (size_t)bh * S_ * S_ + (size_t)q0 * S_;
  float* srow = score_out + (size_t)st * NSC + (size_t)bh * S_ * S_ + (size_t)q0 * S_;
  uint32_t* ofp = ofb + (size_t)st * (NTOK / 2) + (size_t)(b * S_ + q0) * (DH_ / 2) + h * (HD_ / 2);

  const int t = threadIdx.x;
  const int w = t >> 5, lane = t & 31;
  const int gid = lane >> 2, qid = lane & 3;
  const int r0 = w * 16 + gid;

  const uint32_t smb = smem_u32(sm);
  const uint32_t a_off =
      (((lane & 15) * TP) + ((lane >> 4) << 2)) * 4;
  const uint32_t b_off =
      ((((lane & 7) + ((lane >> 4) << 3)) * TP) + (((lane >> 3) & 1) << 2)) * 4;

  auto load_q = [&]() {
#pragma unroll
    for (int i = 0; i < 8; i++) {
      int f = t + i * 256;
      int r = f >> 4, c4 = (f & 15) * 4;
      cp16(&Qs[r * TP + c4], qp + (size_t)r * DH_ + c4);
    }
  };
  auto load_kv = [&](int kbk, int buf) {
#pragma unroll
    for (int i = 0; i < 8; i++) {
      int f = t + i * 256;
      int r = f >> 4, c4 = (f & 15) * 4;
      cp16(&Ks[buf * QK_W + r * TP + c4],
           kp + (size_t)(kbk * 128 + r) * DH_ + c4);
    }
#pragma unroll
    for (int i = 0; i < 4; i++) {
      int f = t + i * 256;
      int r = f >> 4, c4 = (f & 15) * 4;
      cp16(&VT[buf * VT_W + r * TP + c4],
           vtp + (size_t)r * (S_ / 2) + kbk * 64 + c4);
    }
  };

  load_q();
  load_kv(0, 0);
  cp_commit();
  load_kv(1, 1);
  cp_commit();

  float m0 = -1e30f, m1 = -1e30f, l0 = 0.f, l1 = 0.f;
  float oacc[8][4];
#pragma unroll
  for (int j = 0; j < 8; j++)
#pragma unroll
    for (int q = 0; q < 4; q++) oacc[j][q] = 0.f;

  const uint32_t q_base = smb + a_off + (uint32_t)(w * 16 * TP * 4);
  const uint32_t p_base = smb + a_off +
      (uint32_t)((3 * QK_W + 2 * VT_W + w * 16 * TP) * 4);

  for (int it = 0; it < 8; it++) {
    const int buf = it & 1;
    cp_wait<1>();
    __syncthreads();

    float acc[16][4];
#pragma unroll
    for (int nt = 0; nt < 16; nt++)
#pragma unroll
      for (int q = 0; q < 4; q++) acc[nt][q] = 0.f;

#pragma unroll
    for (int kk = 0; kk < 64; kk += 8) {
      uint32_t af[4];
      ldsm4(af, q_base + (uint32_t)(kk * 4));
#pragma unroll
      for (int nt2 = 0; nt2 < 8; nt2++) {
        uint32_t kf[4];
        uint32_t kd = smb + b_off +
            (uint32_t)((QK_W + buf * QK_W + nt2 * 16 * TP + kk) * 4);
        ldsm4(kf, kd);
#pragma unroll
        for (int half = 0; half < 2; half++) {
          const int nt = nt2 * 2 + half;
          uint32_t u0 = kf[half * 2], u1 = kf[half * 2 + 1];
          uint32_t bh2[2] = {__byte_perm(u0, 0, 0x1010), __byte_perm(u1, 0, 0x1010)};
          uint32_t bl2[2] = {__byte_perm(u0, 0, 0x3232), __byte_perm(u1, 0, 0x3232)};
          mma_bf16_k16(acc[nt], af, bh2);
          mma_bf16_k16(acc[nt], af, bl2);
        }
      }
    }

    const int cbase = it * 128;
#pragma unroll
    for (int nt = 0; nt < 16; nt++) {
      int col = cbase + nt * 8 + qid * 2;
      *(float2*)(srow + (size_t)(r0)     * S_ + col) = {acc[nt][0], acc[nt][1]};
      *(float2*)(srow + (size_t)(r0 + 8) * S_ + col) = {acc[nt][2], acc[nt][3]};
      float2 bv0 = *(const float2*)(brow + (size_t)(r0)     * S_ + col);
      float2 bv1 = *(const float2*)(brow + (size_t)(r0 + 8) * S_ + col);
      acc[nt][0] += bv0.x; acc[nt][1] += bv0.y;
      acc[nt][2] += bv1.x; acc[nt][3] += bv1.y;
    }

    float mt0 = -1e30f, mt1 = -1e30f;
#pragma unroll
    for (int nt = 0; nt < 16; nt++) {
      mt0 = fmaxf(mt0, fmaxf(acc[nt][0], acc[nt][1]));
      mt1 = fmaxf(mt1, fmaxf(acc[nt][2], acc[nt][3]));
    }
    mt0 = fmaxf(mt0, __shfl_xor_sync(0xffffffffu, mt0, 1));
    mt0 = fmaxf(mt0, __shfl_xor_sync(0xffffffffu, mt0, 2));
    mt1 = fmaxf(mt1, __shfl_xor_sync(0xffffffffu, mt1, 1));
    mt1 = fmaxf(mt1, __shfl_xor_sync(0xffffffffu, mt1, 2));

    float m0n = fmaxf(m0, mt0), m1n = fmaxf(m1, mt1);
    float sc0 = __expf(m0 - m0n), sc1 = __expf(m1 - m1n);
    m0 = m0n; m1 = m1n;
    l0 *= sc0; l1 *= sc1;
#pragma unroll
    for (int j = 0; j < 8; j++) {
      oacc[j][0] *= sc0; oacc[j][1] *= sc0;
      oacc[j][2] *= sc1; oacc[j][3] *= sc1;
    }

    float ts0 = 0.f, ts1 = 0.f;
#pragma unroll
    for (int nt = 0; nt < 16; nt++) {
      float p00 = __expf(acc[nt][0] - m0);
      float p01 = __expf(acc[nt][1] - m0);
      float p10 = __expf(acc[nt][2] - m1);
      float p11 = __expf(acc[nt][3] - m1);
      ts0 += p00 + p01; ts1 += p10 + p11;
      Ps[(r0)     * TP + nt * 4 + qid] = pack_f16p(p00, p01);
      Ps[(r0 + 8) * TP + nt * 4 + qid] = pack_f16p(p10, p11);
    }
    ts0 += __shfl_xor_sync(0xffffffffu, ts0, 1);
    ts0 += __shfl_xor_sync(0xffffffffu, ts0, 2);
    ts1 += __shfl_xor_sync(0xffffffffu, ts1, 1);
    ts1 += __shfl_xor_sync(0xffffffffu, ts1, 2);
    l0 += ts0; l1 += ts1;
    __syncwarp();

#pragma unroll
    for (int kw = 0; kw < 64; kw += 8) {
      uint32_t ap[4];
      ldsm4(ap, p_base + (uint32_t)(kw * 4));
#pragma unroll
      for (int j2 = 0; j2 < 4; j2++) {
        uint32_t vf[4];
        uint32_t vd = smb + b_off +
            (uint32_t)((3 * QK_W + buf * VT_W + j2 * 16 * TP + kw) * 4);
        ldsm4(vf, vd);
        mma_f16_k16(oacc[j2 * 2],     ap, vf);
        mma_f16_k16(oacc[j2 * 2 + 1], ap, vf + 2);
      }
    }
    __syncthreads();

    if (it + 2 < 8) load_kv(it + 2, buf);
    cp_commit();
  }

  float inv0 = 1.f / l0, inv1 = 1.f / l1;
#pragma unroll
  for (int j = 0; j < 8; j++) {
    int cw = j * 4 + qid;
    ofp[(size_t)(r0)     * (DH_ / 2) + cw] =
        pack_f16p(oacc[j][0] * inv0, oacc[j][1] * inv0);
    ofp[(size_t)(r0 + 8) * (DH_ / 2) + cw] =
        pack_f16p(oacc[j][2] * inv1, oacc[j][3] * inv1);
  }
}

// ---- input packing: all four streams -> f16 pairs ----
__global__ void __launch_bounds__(256) pack_all(
    const float* __restrict__ y, const float* __restrict__ s,
    const float* __restrict__ b, const float* __restrict__ z,
    uint32_t* __restrict__ yfh, uint32_t* __restrict__ sfh,
    uint32_t* __restrict__ bfh, uint32_t* __restrict__ zfh) {
  const int which = blockIdx.y;
  const int i2 = blockIdx.x * 256 + threadIdx.x;
  const float* src; uint32_t* dst; int npair;
  switch (which) {
    case 0: src = y; dst = yfh; npair = M_ * DIN_ / 2; break;
    case 1: src = s; dst = sfh; npair = M_ * DH_ / 2; break;
    case 2: src = b; dst = bfh; npair = M_ * DH_ / 2; break;
    default: src = z; dst = zfh; npair = M_ * DH_ / 2; break;
  }
  if (i2 >= npair) return;
  float2 v = *(const float2*)(src + 2 * i2);
  dst[i2] = pack_f16p(v.x, v.y);
}

// ---- weight transpose: all -> f16 pairs [n][K/2] ----
struct WEnt { const float* src; uint32_t* dst; int K; };
struct WTab { WEnt e[12]; };

__global__ void __launch_bounds__(256) transpose_w(const WTab tab) {
  WEnt e = tab.e[blockIdx.z];
  int n0 = blockIdx.x * 32, k0 = blockIdx.y * 32;
  if (k0 >= e.K) return;
  __shared__ float tl[32][33];
  int tx = threadIdx.x, ty = threadIdx.y;
#pragma unroll
  for (int i = 0; i < 32; i += 8)
    tl[ty + i][tx] = e.src[(size_t)(k0 + ty + i) * DH_ + n0 + tx];
  __syncthreads();
  if (tx < 16) {
#pragma unroll
    for (int i = 0; i < 32; i += 8) {
      int nn = ty + i;
      e.dst[(size_t)(n0 + nn) * (e.K / 2) + k0 / 2 + tx] =
          pack_f16p(tl[2 * tx][nn], tl[2 * tx + 1][nn]);
    }
  }
}

// ---- V transpose ----
__global__ void __launch_bounds__(256) transpose_v(const float* __restrict__ v,
                                                   uint32_t* __restrict__ vt) {
  int z = blockIdx.z, st = z >> 5, bh = z & 31, b = bh >> 4, h = bh & 15;
  int c0 = blockIdx.x * 32, k0 = blockIdx.y * 32;
  __shared__ float tl[32][33];
  int tx = threadIdx.x, ty = threadIdx.y;
  const float* src = v + (size_t)st * NTOK + (size_t)b * S_ * DH_ + h * HD_;
  uint32_t* dst = vt + (size_t)z * (HD_ * S_ / 2);
#pragma unroll
  for (int i = 0; i < 32; i += 8)
    tl[ty + i][tx] = src[(size_t)(k0 + ty + i) * DH_ + c0 + tx];
  __syncthreads();
  if (tx < 16) {
#pragma unroll
    for (int i = 0; i < 32; i += 8) {
      int cc = ty + i;
      dst[(size_t)(c0 + cc) * (S_ / 2) + k0 / 2 + tx] =
          pack_f16p(tl[2 * tx][cc], tl[2 * tx + 1][cc]);
    }
  }
}

// ---- residual chain ----
__global__ void __launch_bounds__(256) combine_kernel(
    const float* __restrict__ s, const float* __restrict__ b,
    const float* __restrict__ z, const float* __restrict__ ps,
    const float* __restrict__ pb, const float* __restrict__ pz,
    float* __restrict__ os, float* __restrict__ ob, float* __restrict__ oz) {
  size_t i = (size_t)blockIdx.x * 256 + threadIdx.x;
  if (i >= NTOK) return;
  float so = s[i] + ps[i];
  float bo = so + b[i] + pb[i];
  float zo = bo + z[i] + pz[i];
  os[i] = so; ob[i] = bo; oz[i] = zo;
}

// ===========================================================================
extern "C" void kernel_launch(void* const* d_in, const int* in_sizes, int n_in,
                              void* d_out, int out_size) {
  const float* y    = (const float*)d_in[0];
  const float* s    = (const float*)d_in[1];
  const float* b    = (const float*)d_in[2];
  const float* z    = (const float*)d_in[3];
  const float* ba0  = (const float*)d_in[4];
  const float* ba1  = (const float*)d_in[5];
  const float* ba2  = (const float*)d_in[6];
  const float* W[12] = {
      (const float*)d_in[7],  (const float*)d_in[9],  (const float*)d_in[11],
      (const float*)d_in[13], (const float*)d_in[15], (const float*)d_in[17],
      (const float*)d_in[19], (const float*)d_in[21],
      (const float*)d_in[23], (const float*)d_in[25], (const float*)d_in[27],
      (const float*)d_in[29]};
  const float* C[12] = {
      (const float*)d_in[8],  (const float*)d_in[10], (const float*)d_in[12],
      (const float*)d_in[14], (const float*)d_in[16], (const float*)d_in[18],
      (const float*)d_in[20], (const float*)d_in[22],
      (const float*)d_in[24], (const float*)d_in[26], (const float*)d_in[28],
      (const float*)d_in[30]};
  const int KW[12] = {DIN_, DIN_, DIN_, DH_, DH_, DH_, DH_, DH_,
                      DH_, DH_, DH_, DH_};

  float* out   = (float*)d_out;
  float* s_out = out;
  float* b_out = out + NTOK;
  float* z_out = out + 2 * NTOK;
  float* scb   = out + 3 * NTOK;

  uint32_t *gq, *gk, *gof, *gwtf, *gvth, *gyf, *gsf, *gbf, *gzf;
  float *gv, *gp;
  cudaGetSymbolAddress((void**)&gq, g_q);
  cudaGetSymbolAddress((void**)&gk, g_k);
  cudaGetSymbolAddress((void**)&gv, g_v);
  cudaGetSymbolAddress((void**)&gof, g_of);
  cudaGetSymbolAddress((void**)&gp, g_p);
  cudaGetSymbolAddress((void**)&gwtf, g_wtf);
  cudaGetSymbolAddress((void**)&gvth, g_vth);
  cudaGetSymbolAddress((void**)&gyf, g_yfh);
  cudaGetSymbolAddress((void**)&gsf, g_sfh);
  cudaGetSymbolAddress((void**)&gbf, g_bfh);
  cudaGetSymbolAddress((void**)&gzf, g_zfh);

  cudaFuncSetAttribute(fused_attn, cudaFuncAttributeMaxDynamicSharedMemorySize,
                       FUSED_SMEM);
  cudaFuncSetAttribute(proj_mixed, cudaFuncAttributeMaxDynamicSharedMemorySize,
                       GEMM_SMEM);

  // --- 1a: pack all inputs to f16 pairs ---
  pack_all<<<dim3(4096, 4), 256>>>(y, s, b, z, gyf, gsf, gbf, gzf);

  // --- 1b: transpose all weights to f16 pairs ---
  WTab wt{};
  for (int i = 0; i < 12; i++)
    wt.e[i] = {W[i], gwtf + (size_t)i * (DH_ * DH_ / 2), KW[i]};
  transpose_w<<<dim3(32, 32, 12), dim3(32, 8)>>>(wt);

  auto WTf = [&](int i) -> const uint32_t* {
    return gwtf + (size_t)i * (DH_ * DH_ / 2);
  };

  // --- 2: ALL 9 projection ops in ONE launch (heavy first) ---
  // weight idx: 0 qs 1 qb 2 qz 3 kss 4 ksb 5 kzb 6 kbb 7 kzz 8 vs 9 vb 10 vz 11 o
  OpTable tab{};
  auto setp = [&](int idx, uint32_t* Cp, int Kw, int nt, int mode,
                  const uint32_t* A0, int w0,
                  const uint32_t* A1 = nullptr, int w1 = -1,
                  const uint32_t* A2 = nullptr, int w2 = -1) {
    Op& o = tab.op[idx];
    o.C = (float*)Cp; o.K = Kw; o.nt = nt; o.lda = Kw; o.ldb = Kw; o.ldc = DH_;
    o.mode = mode;
    o.t[0] = {A0, WTf(w0), C[w0]};
    if (nt > 1) o.t[1] = {A1, WTf(w1), C[w1]};
    if (nt > 2) o.t[2] = {A2, WTf(w2), C[w2]};
  };
  // heavy -> light: 3-term K, 2-term K x2, V x3, Q x3
  setp(0, gk + 1 * NTOK, DH_ / 2, 3, 2, gbf, 6, gsf, 4, gzf, 5);
  setp(1, gk + 0 * NTOK, DH_ / 2, 2, 2, gsf, 3, gbf, 4);
  setp(2, gk + 2 * NTOK, DH_ / 2, 2, 2, gzf, 7, gbf, 5);
  setp(3, (uint32_t*)(gv + 0 * NTOK), DH_ / 2, 1, 0, gsf, 8);
  setp(4, (uint32_t*)(gv + 1 * NTOK), DH_ / 2, 1, 0, gbf, 9);
  setp(5, (uint32_t*)(gv + 2 * NTOK), DH_ / 2, 1, 0, gzf, 10);
  setp(6, gq + 0 * NTOK, DIN_ / 2, 1, 2, gyf, 0);
  setp(7, gq + 1 * NTOK, DIN_ / 2, 1, 2, gyf, 1);
  setp(8, gq + 2 * NTOK, DIN_ / 2, 1, 2, gyf, 2);
  proj_mixed<<<dim3(8, 16, 9), 256, GEMM_SMEM>>>(tab);

  // --- 3: V transpose ---
  transpose_v<<<dim3(2, 32, 96), dim3(32, 8)>>>(gv, gvth);

  // --- 4: fused attention ---
  fused_attn<<<dim3(8, 96), 256, FUSED_SMEM>>>(gq, gk, gvth, ba0, ba1, ba2,
                                               scb, gof);

  // --- 5: output projections (f16) ---
  OpTable to{};
  for (int i = 0; i < 3; i++) {
    Op& o = to.op[i];
    o.C = gp + (size_t)i * NTOK; o.K = DH_ / 2; o.nt = 1;
    o.lda = DH_ / 2; o.ldb = DH_ / 2; o.ldc = DH_;
    o.mode = 0;
    o.t[0] = {gof + (size_t)i * (NTOK / 2), WTf(11), C[11]};
  }
  proj_mixed<<<dim3(8, 16, 3), 256, GEMM_SMEM>>>(to);

  // --- 6: residual chain ---
  combine_kernel<<<(int)((NTOK + 255) / 256), 256>>>(
      s, b, z, gp + 0 * NTOK, gp + 1 * NTOK, gp + 2 * NTOK,
      s_out, b_out, z_out);
}

// round 15
// speedup vs baseline: 2.0586x; 1.1424x over previous
#include <cuda_runtime.h>
#include <cuda_fp16.h>
#include <cstdint>
#include <math.h>

// ===========================================================================
// MarkovBlanketAttention on sm_103 — R14: all-f16 MMA everywhere.
// Q/K stored as f16 pairs; scores GEMM f16-single (4x fewer MMA instr than
// bf16x2 2-MMA). fp32 accumulate throughout. R13 structure otherwise kept.
// ===========================================================================

namespace {
constexpr int B_   = 2;
constexpr int S_   = 1024;
constexpr int DIN_ = 512;
constexpr int DH_  = 1024;
constexpr int H_   = 16;
constexpr int HD_  = 64;
constexpr int M_   = B_ * S_;
constexpr size_t NTOK = (size_t)M_ * DH_;
constexpr size_t NSC  = (size_t)B_ * H_ * S_ * S_;
}

// ---- scratch (device globals) ----
__device__ uint32_t g_q[3][NTOK / 2];         // f16-pair Q
__device__ uint32_t g_k[3][NTOK / 2];         // f16-pair K
__device__ float    g_v[3][NTOK];
__device__ uint32_t g_of[3][NTOK / 2];        // attn out, f16 pairs
__device__ float    g_p[3][NTOK];
__device__ uint32_t g_wtf[12][DH_ * DH_ / 2]; // weights^T, f16 pairs
__device__ uint32_t g_vth[96][HD_ * S_ / 2];
__device__ uint32_t g_yfh[M_ * DIN_ / 2];
__device__ uint32_t g_sfh[M_ * DH_ / 2];
__device__ uint32_t g_bfh[M_ * DH_ / 2];
__device__ uint32_t g_zfh[M_ * DH_ / 2];

// ---------------------------------------------------------------------------
// helpers
// ---------------------------------------------------------------------------
__device__ __forceinline__ uint32_t smem_u32(const void* p) {
  uint32_t a;
  asm("{ .reg .u64 t; cvta.to.shared.u64 t, %1; cvt.u32.u64 %0, t; }"
      : "=r"(a) : "l"(p));
  return a;
}
__device__ __forceinline__ void cp16(void* smem, const void* g) {
  asm volatile("cp.async.cg.shared.global [%0], [%1], 16;"
               :: "r"(smem_u32(smem)), "l"(g));
}
__device__ __forceinline__ void cp_commit() {
  asm volatile("cp.async.commit_group;" ::: "memory");
}
template <int N>
__device__ __forceinline__ void cp_wait() {
  asm volatile("cp.async.wait_group %0;" :: "n"(N) : "memory");
}
__device__ __forceinline__ void ldsm4(uint32_t* r, uint32_t addr) {
  asm volatile(
      "ldmatrix.sync.aligned.m8n8.x4.shared.b16 {%0,%1,%2,%3}, [%4];"
      : "=r"(r[0]), "=r"(r[1]), "=r"(r[2]), "=r"(r[3]) : "r"(addr));
}
__device__ __forceinline__ void mma_f16_k16(float* c, const uint32_t* a,
                                            const uint32_t* b) {
  asm volatile(
      "mma.sync.aligned.m16n8k16.row.col.f32.f16.f16.f32 "
      "{%0,%1,%2,%3}, {%4,%5,%6,%7}, {%8,%9}, {%0,%1,%2,%3};"
      : "+f"(c[0]), "+f"(c[1]), "+f"(c[2]), "+f"(c[3])
      : "r"(a[0]), "r"(a[1]), "r"(a[2]), "r"(a[3]), "r"(b[0]), "r"(b[1]));
}
__device__ __forceinline__ uint32_t pack_f16p(float a, float b) {
  __half2 h = __floats2half2_rn(a, b);
  return *(uint32_t*)&h;
}

// ---------------------------------------------------------------------------
// GEMM core: BK=32 words, pitch 36, double buffer, f16 MMA.
// PACKHALF: epilogue writes f16 pairs (ldc in words); else fp32 (ldc floats).
// ---------------------------------------------------------------------------
struct Term { const uint32_t* A; const uint32_t* W; const float* bias; };
struct Op   { Term t[3]; float* C; int nt; int K; int lda; int ldb; int ldc;
              int mode; int pad; };
struct OpTable { Op op[9]; };

namespace {
constexpr int GBK = 32;
constexpr int GPITCH = 36;
constexpr int GTILE = 128 * GPITCH;
constexpr int GEMM_SMEM = 4 * GTILE * 4;   // 73728 B
}

template <int BN, bool PACKHALF>
__device__ __forceinline__ void gemm_core(const Op& op, uint32_t* dsm) {
  constexpr int WN = BN / 2;
  constexpr int NT = WN / 8;
  uint32_t* As = dsm;
  uint32_t* Bs = dsm + 2 * GTILE;

  const int t = threadIdx.x;
  const int wid = t >> 5, lane = t & 31;
  const int warp_m = wid & 3;
  const int wn = wid >> 2;
  const int gid = lane >> 2, qid = lane & 3;

  const int bm = blockIdx.y * 128;
  const int bn = blockIdx.x * BN;
  const int cpt = op.K / GBK;
  const int total = op.nt * cpt;

  const uint32_t asb = smem_u32(As);
  const uint32_t bsb = smem_u32(Bs);
  const uint32_t a_off =
      (((lane & 15) * GPITCH) + ((lane >> 4) << 2)) * 4;
  const uint32_t b_off =
      ((((lane & 7) + ((lane >> 4) << 3)) * GPITCH) + (((lane >> 3) & 1) << 2)) * 4;

  float acc[2][NT][4];
#pragma unroll
  for (int mt = 0; mt < 2; mt++)
#pragma unroll
    for (int nt = 0; nt < NT; nt++)
#pragma unroll
      for (int j = 0; j < 4; j++) acc[mt][nt][j] = 0.f;

  auto load_chunk = [&](int c, int buf) {
    const int term = c / cpt;
    const int k0 = (c - term * cpt) * GBK;
    const uint32_t* __restrict__ A = op.t[term].A;
    const uint32_t* __restrict__ W = op.t[term].W;
#pragma unroll
    for (int i = 0; i < 4; i++) {
      int f = t + i * 256;
      int r = f >> 3, c4 = (f & 7) * 4;
      cp16(&As[buf * GTILE + r * GPITCH + c4],
           A + (size_t)(bm + r) * op.lda + k0 + c4);
    }
#pragma unroll
    for (int i = 0; i < BN / 32; i++) {
      int f = t + i * 256;
      int r = f >> 3, c4 = (f & 7) * 4;
      cp16(&Bs[buf * GTILE + r * GPITCH + c4],
           W + (size_t)(bn + r) * op.ldb + k0 + c4);
    }
  };

  load_chunk(0, 0);
  cp_commit();

  for (int c = 0; c < total; c++) {
    const int buf = c & 1;
    if (c + 1 < total) load_chunk(c + 1, (c + 1) & 1);
    cp_commit();
    cp_wait<1>();
    __syncthreads();

#pragma unroll
    for (int kk = 0; kk < GBK; kk += 8) {
      uint32_t af[2][4];
#pragma unroll
      for (int mt = 0; mt < 2; mt++) {
        uint32_t ad = asb + a_off +
            (uint32_t)((buf * GTILE + (warp_m * 32 + mt * 16) * GPITCH + kk) * 4);
        ldsm4(af[mt], ad);
      }
#pragma unroll
      for (int nt2 = 0; nt2 < NT / 2; nt2++) {
        uint32_t bf[4];
        uint32_t bd = bsb + b_off +
            (uint32_t)((buf * GTILE + (wn * WN + nt2 * 16) * GPITCH + kk) * 4);
        ldsm4(bf, bd);
#pragma unroll
        for (int half = 0; half < 2; half++) {
          const int nt = nt2 * 2 + half;
#pragma unroll
          for (int mt = 0; mt < 2; mt++)
            mma_f16_k16(acc[mt][nt], af[mt], bf + half * 2);
        }
      }
    }
    __syncthreads();
  }

#pragma unroll
  for (int mt = 0; mt < 2; mt++) {
    int row0 = bm + warp_m * 32 + mt * 16 + gid;
#pragma unroll
    for (int nt = 0; nt < NT; nt++) {
      int col = bn + wn * WN + nt * 8 + qid * 2;
      float b0 = 0.f, b1 = 0.f;
      if (op.t[0].bias) {
        for (int tt = 0; tt < op.nt; tt++) {
          b0 += op.t[tt].bias[col];
          b1 += op.t[tt].bias[col + 1];
        }
      }
      float v00 = acc[mt][nt][0] + b0, v01 = acc[mt][nt][1] + b1;
      float v10 = acc[mt][nt][2] + b0, v11 = acc[mt][nt][3] + b1;
      if (PACKHALF) {
        uint32_t* Cp = (uint32_t*)op.C;
        int colw = (bn + wn * WN + nt * 8) / 2 + qid;
        Cp[(size_t)row0 * op.ldc + colw]       = pack_f16p(v00, v01);
        Cp[(size_t)(row0 + 8) * op.ldc + colw] = pack_f16p(v10, v11);
      } else {
        *(float2*)(op.C + (size_t)row0 * op.ldc + col) = {v00, v01};
        *(float2*)(op.C + (size_t)(row0 + 8) * op.ldc + col) = {v10, v11};
      }
    }
  }
}

// Mixed-mode projection kernel: mode 2 = f16-pair output (Q/K), else fp32.
__global__ void __launch_bounds__(256) proj_mixed(const OpTable tab) {
  extern __shared__ uint32_t ds[];
  const Op& op = tab.op[blockIdx.z];
  if (op.mode == 2)
    gemm_core<128, true>(op, ds);
  else
    gemm_core<128, false>(op, ds);
}

// ---------------------------------------------------------------------------
// Fused attention: f16 Q/K (32-word rows, pitch 36), f16 scores + PV.
// ---------------------------------------------------------------------------
namespace {
constexpr int QP = 36;                  // Q/K tile pitch (words)
constexpr int QW = 128 * QP;            // 4608 words per Q/K tile
constexpr int VTP = 68;                 // VT/Ps pitch
constexpr int VT_W = 64 * VTP;          // 4352 words per VT tile
constexpr int PS_OFF = 3 * QW + 2 * VT_W;       // 22528
constexpr int FUSED_SMEM = (PS_OFF + 128 * VTP) * 4;  // 124928 B
}

__global__ void __launch_bounds__(256) fused_attn(
    const uint32_t* __restrict__ qb, const uint32_t* __restrict__ kb,
    const uint32_t* __restrict__ vtb, const float* __restrict__ bias0,
    const float* __restrict__ bias1, const float* __restrict__ bias2,
    float* __restrict__ score_out, uint32_t* __restrict__ ofb) {
  extern __shared__ uint32_t sm[];
  uint32_t* Qs = sm;                    // [128][QP]
  uint32_t* Ks = sm + QW;               // [2][128][QP]
  uint32_t* VT = sm + 3 * QW;           // [2][64][VTP]
  uint32_t* Ps = sm + PS_OFF;           // [128][VTP]

  const int zz = blockIdx.y;
  const int st = zz >> 5, bh = zz & 31, b = bh >> 4, h = bh & 15;
  const int q0 = blockIdx.x * 128;

  const uint32_t* qp = qb + (size_t)st * (NTOK / 2) +
                       (size_t)(b * S_ + q0) * (DH_ / 2) + h * (HD_ / 2);
  const uint32_t* kp = kb + (size_t)st * (NTOK / 2) +
                       (size_t)b * S_ * (DH_ / 2) + h * (HD_ / 2);
  const uint32_t* vtp = vtb + (size_t)zz * (HD_ * S_ / 2);
  const float* bias = (st == 0) ? bias0 : (st == 1) ? bias1 : bias2;
  const float* brow = bias + (size_t)bh * S_ * S_ + (size_t)q0 * S_;
  float* srow = score_out + (size_t)st * NSC + (size_t)bh * S_ * S_ + (size_t)q0 * S_;
  uint32_t* ofp = ofb + (size_t)st * (NTOK / 2) +
                  (size_t)(b * S_ + q0) * (DH_ / 2) + h * (HD_ / 2);

  const int t = threadIdx.x;
  const int w = t >> 5, lane = t & 31;
  const int gid = lane >> 2, qid = lane & 3;
  const int r0 = w * 16 + gid;

  const uint32_t smb = smem_u32(sm);
  const uint32_t a36 =
      (((lane & 15) * QP) + ((lane >> 4) << 2)) * 4;
  const uint32_t b36 =
      ((((lane & 7) + ((lane >> 4) << 3)) * QP) + (((lane >> 3) & 1) << 2)) * 4;
  const uint32_t a68 =
      (((lane & 15) * VTP) + ((lane >> 4) << 2)) * 4;
  const uint32_t b68 =
      ((((lane & 7) + ((lane >> 4) << 3)) * VTP) + (((lane >> 3) & 1) << 2)) * 4;

  auto load_q = [&]() {
#pragma unroll
    for (int i = 0; i < 4; i++) {        // 128 rows x 32 words
      int f = t + i * 256;
      int r = f >> 3, c4 = (f & 7) * 4;
      cp16(&Qs[r * QP + c4], qp + (size_t)r * (DH_ / 2) + c4);
    }
  };
  auto load_kv = [&](int kbk, int buf) {
#pragma unroll
    for (int i = 0; i < 4; i++) {        // K tile: 128 x 32 words
      int f = t + i * 256;
      int r = f >> 3, c4 = (f & 7) * 4;
      cp16(&Ks[buf * QW + r * QP + c4],
           kp + (size_t)(kbk * 128 + r) * (DH_ / 2) + c4);
    }
#pragma unroll
    for (int i = 0; i < 4; i++) {        // VT tile: 64 rows x 64 words
      int f = t + i * 256;
      int r = f >> 4, c4 = (f & 15) * 4;
      cp16(&VT[buf * VT_W + r * VTP + c4],
           vtp + (size_t)r * (S_ / 2) + kbk * 64 + c4);
    }
  };

  load_q();
  load_kv(0, 0);
  cp_commit();
  load_kv(1, 1);
  cp_commit();

  float m0 = -1e30f, m1 = -1e30f, l0 = 0.f, l1 = 0.f;
  float oacc[8][4];
#pragma unroll
  for (int j = 0; j < 8; j++)
#pragma unroll
    for (int q = 0; q < 4; q++) oacc[j][q] = 0.f;

  const uint32_t q_base = smb + a36 + (uint32_t)(w * 16 * QP * 4);
  const uint32_t p_base = smb + a68 + (uint32_t)((PS_OFF + w * 16 * VTP) * 4);

  for (int it = 0; it < 8; it++) {
    const int buf = it & 1;
    cp_wait<1>();
    __syncthreads();

    // ---- scores: f16 single MMA (4 kk-steps of 8 words = 64 true k) ----
    float acc[16][4];
#pragma unroll
    for (int nt = 0; nt < 16; nt++)
#pragma unroll
      for (int q = 0; q < 4; q++) acc[nt][q] = 0.f;

#pragma unroll
    for (int kk = 0; kk < 32; kk += 8) {
      uint32_t af[4];
      ldsm4(af, q_base + (uint32_t)(kk * 4));
#pragma unroll
      for (int nt2 = 0; nt2 < 8; nt2++) {
        uint32_t kf[4];
        uint32_t kd = smb + b36 +
            (uint32_t)((QW + buf * QW + nt2 * 16 * QP + kk) * 4);
        ldsm4(kf, kd);
        mma_f16_k16(acc[nt2 * 2],     af, kf);
        mma_f16_k16(acc[nt2 * 2 + 1], af, kf + 2);
      }
    }

    // ---- raw scores out, add bias ----
    const int cbase = it * 128;
#pragma unroll
    for (int nt = 0; nt < 16; nt++) {
      int col = cbase + nt * 8 + qid * 2;
      *(float2*)(srow + (size_t)(r0)     * S_ + col) = {acc[nt][0], acc[nt][1]};
      *(float2*)(srow + (size_t)(r0 + 8) * S_ + col) = {acc[nt][2], acc[nt][3]};
      float2 bv0 = *(const float2*)(brow + (size_t)(r0)     * S_ + col);
      float2 bv1 = *(const float2*)(brow + (size_t)(r0 + 8) * S_ + col);
      acc[nt][0] += bv0.x; acc[nt][1] += bv0.y;
      acc[nt][2] += bv1.x; acc[nt][3] += bv1.y;
    }

    // ---- online softmax ----
    float mt0 = -1e30f, mt1 = -1e30f;
#pragma unroll
    for (int nt = 0; nt < 16; nt++) {
      mt0 = fmaxf(mt0, fmaxf(acc[nt][0], acc[nt][1]));
      mt1 = fmaxf(mt1, fmaxf(acc[nt][2], acc[nt][3]));
    }
    mt0 = fmaxf(mt0, __shfl_xor_sync(0xffffffffu, mt0, 1));
    mt0 = fmaxf(mt0, __shfl_xor_sync(0xffffffffu, mt0, 2));
    mt1 = fmaxf(mt1, __shfl_xor_sync(0xffffffffu, mt1, 1));
    mt1 = fmaxf(mt1, __shfl_xor_sync(0xffffffffu, mt1, 2));

    float m0n = fmaxf(m0, mt0), m1n = fmaxf(m1, mt1);
    float sc0 = __expf(m0 - m0n), sc1 = __expf(m1 - m1n);
    m0 = m0n; m1 = m1n;
    l0 *= sc0; l1 *= sc1;
#pragma unroll
    for (int j = 0; j < 8; j++) {
      oacc[j][0] *= sc0; oacc[j][1] *= sc0;
      oacc[j][2] *= sc1; oacc[j][3] *= sc1;
    }

    float ts0 = 0.f, ts1 = 0.f;
#pragma unroll
    for (int nt = 0; nt < 16; nt++) {
      float p00 = __expf(acc[nt][0] - m0);
      float p01 = __expf(acc[nt][1] - m0);
      float p10 = __expf(acc[nt][2] - m1);
      float p11 = __expf(acc[nt][3] - m1);
      ts0 += p00 + p01; ts1 += p10 + p11;
      Ps[(r0)     * VTP + nt * 4 + qid] = pack_f16p(p00, p01);
      Ps[(r0 + 8) * VTP + nt * 4 + qid] = pack_f16p(p10, p11);
    }
    ts0 += __shfl_xor_sync(0xffffffffu, ts0, 1);
    ts0 += __shfl_xor_sync(0xffffffffu, ts0, 2);
    ts1 += __shfl_xor_sync(0xffffffffu, ts1, 1);
    ts1 += __shfl_xor_sync(0xffffffffu, ts1, 2);
    l0 += ts0; l1 += ts1;
    __syncwarp();

    // ---- PV ----
#pragma unroll
    for (int kw = 0; kw < 64; kw += 8) {
      uint32_t ap[4];
      ldsm4(ap, p_base + (uint32_t)(kw * 4));
#pragma unroll
      for (int j2 = 0; j2 < 4; j2++) {
        uint32_t vf[4];
        uint32_t vd = smb + b68 +
            (uint32_t)((3 * QW + buf * VT_W + j2 * 16 * VTP + kw) * 4);
        ldsm4(vf, vd);
        mma_f16_k16(oacc[j2 * 2],     ap, vf);
        mma_f16_k16(oacc[j2 * 2 + 1], ap, vf + 2);
      }
    }
    __syncthreads();

    if (it + 2 < 8) load_kv(it + 2, buf);
    cp_commit();
  }

  float inv0 = 1.f / l0, inv1 = 1.f / l1;
#pragma unroll
  for (int j = 0; j < 8; j++) {
    int cw = j * 4 + qid;
    ofp[(size_t)(r0)     * (DH_ / 2) + cw] =
        pack_f16p(oacc[j][0] * inv0, oacc[j][1] * inv0);
    ofp[(size_t)(r0 + 8) * (DH_ / 2) + cw] =
        pack_f16p(oacc[j][2] * inv1, oacc[j][3] * inv1);
  }
}

// ---- input packing: all four streams -> f16 pairs ----
__global__ void __launch_bounds__(256) pack_all(
    const float* __restrict__ y, const float* __restrict__ s,
    const float* __restrict__ b, const float* __restrict__ z,
    uint32_t* __restrict__ yfh, uint32_t* __restrict__ sfh,
    uint32_t* __restrict__ bfh, uint32_t* __restrict__ zfh) {
  const int which = blockIdx.y;
  const int i2 = blockIdx.x * 256 + threadIdx.x;
  const float* src; uint32_t* dst; int npair;
  switch (which) {
    case 0: src = y; dst = yfh; npair = M_ * DIN_ / 2; break;
    case 1: src = s; dst = sfh; npair = M_ * DH_ / 2; break;
    case 2: src = b; dst = bfh; npair = M_ * DH_ / 2; break;
    default: src = z; dst = zfh; npair = M_ * DH_ / 2; break;
  }
  if (i2 >= npair) return;
  float2 v = *(const float2*)(src + 2 * i2);
  dst[i2] = pack_f16p(v.x, v.y);
}

// ---- weight transpose: all -> f16 pairs [n][K/2] ----
struct WEnt { const float* src; uint32_t* dst; int K; };
struct WTab { WEnt e[12]; };

__global__ void __launch_bounds__(256) transpose_w(const WTab tab) {
  WEnt e = tab.e[blockIdx.z];
  int n0 = blockIdx.x * 32, k0 = blockIdx.y * 32;
  if (k0 >= e.K) return;
  __shared__ float tl[32][33];
  int tx = threadIdx.x, ty = threadIdx.y;
#pragma unroll
  for (int i = 0; i < 32; i += 8)
    tl[ty + i][tx] = e.src[(size_t)(k0 + ty + i) * DH_ + n0 + tx];
  __syncthreads();
  if (tx < 16) {
#pragma unroll
    for (int i = 0; i < 32; i += 8) {
      int nn = ty + i;
      e.dst[(size_t)(n0 + nn) * (e.K / 2) + k0 / 2 + tx] =
          pack_f16p(tl[2 * tx][nn], tl[2 * tx + 1][nn]);
    }
  }
}

// ---- V transpose ----
__global__ void __launch_bounds__(256) transpose_v(const float* __restrict__ v,
                                                   uint32_t* __restrict__ vt) {
  int z = blockIdx.z, st = z >> 5, bh = z & 31, b = bh >> 4, h = bh & 15;
  int c0 = blockIdx.x * 32, k0 = blockIdx.y * 32;
  __shared__ float tl[32][33];
  int tx = threadIdx.x, ty = threadIdx.y;
  const float* src = v + (size_t)st * NTOK + (size_t)b * S_ * DH_ + h * HD_;
  uint32_t* dst = vt + (size_t)z * (HD_ * S_ / 2);
#pragma unroll
  for (int i = 0; i < 32; i += 8)
    tl[ty + i][tx] = src[(size_t)(k0 + ty + i) * DH_ + c0 + tx];
  __syncthreads();
  if (tx < 16) {
#pragma unroll
    for (int i = 0; i < 32; i += 8) {
      int cc = ty + i;
      dst[(size_t)(c0 + cc) * (S_ / 2) + k0 / 2 + tx] =
          pack_f16p(tl[2 * tx][cc], tl[2 * tx + 1][cc]);
    }
  }
}

// ---- residual chain ----
__global__ void __launch_bounds__(256) combine_kernel(
    const float* __restrict__ s, const float* __restrict__ b,
    const float* __restrict__ z, const float* __restrict__ ps,
    const float* __restrict__ pb, const float* __restrict__ pz,
    float* __restrict__ os, float* __restrict__ ob, float* __restrict__ oz) {
  size_t i = (size_t)blockIdx.x * 256 + threadIdx.x;
  if (i >= NTOK) return;
  float so = s[i] + ps[i];
  float bo = so + b[i] + pb[i];
  float zo = bo + z[i] + pz[i];
  os[i] = so; ob[i] = bo; oz[i] = zo;
}

// ===========================================================================
extern "C" void kernel_launch(void* const* d_in, const int* in_sizes, int n_in,
                              void* d_out, int out_size) {
  const float* y    = (const float*)d_in[0];
  const float* s    = (const float*)d_in[1];
  const float* b    = (const float*)d_in[2];
  const float* z    = (const float*)d_in[3];
  const float* ba0  = (const float*)d_in[4];
  const float* ba1  = (const float*)d_in[5];
  const float* ba2  = (const float*)d_in[6];
  const float* W[12] = {
      (const float*)d_in[7],  (const float*)d_in[9],  (const float*)d_in[11],
      (const float*)d_in[13], (const float*)d_in[15], (const float*)d_in[17],
      (const float*)d_in[19], (const float*)d_in[21],
      (const float*)d_in[23], (const float*)d_in[25], (const float*)d_in[27],
      (const float*)d_in[29]};
  const float* C[12] = {
      (const float*)d_in[8],  (const float*)d_in[10], (const float*)d_in[12],
      (const float*)d_in[14], (const float*)d_in[16], (const float*)d_in[18],
      (const float*)d_in[20], (const float*)d_in[22],
      (const float*)d_in[24], (const float*)d_in[26], (const float*)d_in[28],
      (const float*)d_in[30]};
  const int KW[12] = {DIN_, DIN_, DIN_, DH_, DH_, DH_, DH_, DH_,
                      DH_, DH_, DH_, DH_};

  float* out   = (float*)d_out;
  float* s_out = out;
  float* b_out = out + NTOK;
  float* z_out = out + 2 * NTOK;
  float* scb   = out + 3 * NTOK;

  uint32_t *gq, *gk, *gof, *gwtf, *gvth, *gyf, *gsf, *gbf, *gzf;
  float *gv, *gp;
  cudaGetSymbolAddress((void**)&gq, g_q);
  cudaGetSymbolAddress((void**)&gk, g_k);
  cudaGetSymbolAddress((void**)&gv, g_v);
  cudaGetSymbolAddress((void**)&gof, g_of);
  cudaGetSymbolAddress((void**)&gp, g_p);
  cudaGetSymbolAddress((void**)&gwtf, g_wtf);
  cudaGetSymbolAddress((void**)&gvth, g_vth);
  cudaGetSymbolAddress((void**)&gyf, g_yfh);
  cudaGetSymbolAddress((void**)&gsf, g_sfh);
  cudaGetSymbolAddress((void**)&gbf, g_bfh);
  cudaGetSymbolAddress((void**)&gzf, g_zfh);

  cudaFuncSetAttribute(fused_attn, cudaFuncAttributeMaxDynamicSharedMemorySize,
                       FUSED_SMEM);
  cudaFuncSetAttribute(proj_mixed, cudaFuncAttributeMaxDynamicSharedMemorySize,
                       GEMM_SMEM);

  // --- 1a: pack all inputs to f16 pairs ---
  pack_all<<<dim3(4096, 4), 256>>>(y, s, b, z, gyf, gsf, gbf, gzf);

  // --- 1b: transpose all weights to f16 pairs ---
  WTab wt{};
  for (int i = 0; i < 12; i++)
    wt.e[i] = {W[i], gwtf + (size_t)i * (DH_ * DH_ / 2), KW[i]};
  transpose_w<<<dim3(32, 32, 12), dim3(32, 8)>>>(wt);

  auto WTf = [&](int i) -> const uint32_t* {
    return gwtf + (size_t)i * (DH_ * DH_ / 2);
  };

  // --- 2: ALL 9 projection ops in ONE launch (heavy first) ---
  // weight idx: 0 qs 1 qb 2 qz 3 kss 4 ksb 5 kzb 6 kbb 7 kzz 8 vs 9 vb 10 vz 11 o
  OpTable tab{};
  auto setp = [&](int idx, void* Cp, int Kw, int nt, int mode,
                  const uint32_t* A0, int w0,
                  const uint32_t* A1 = nullptr, int w1 = -1,
                  const uint32_t* A2 = nullptr, int w2 = -1) {
    Op& o = tab.op[idx];
    o.C = (float*)Cp; o.K = Kw; o.nt = nt; o.lda = Kw; o.ldb = Kw;
    o.ldc = (mode == 2) ? DH_ / 2 : DH_;
    o.mode = mode;
    o.t[0] = {A0, WTf(w0), C[w0]};
    if (nt > 1) o.t[1] = {A1, WTf(w1), C[w1]};
    if (nt > 2) o.t[2] = {A2, WTf(w2), C[w2]};
  };
  // heavy -> light: 3-term K, 2-term K x2, V x3, Q x3
  setp(0, gk + 1 * (NTOK / 2), DH_ / 2, 3, 2, gbf, 6, gsf, 4, gzf, 5);
  setp(1, gk + 0 * (NTOK / 2), DH_ / 2, 2, 2, gsf, 3, gbf, 4);
  setp(2, gk + 2 * (NTOK / 2), DH_ / 2, 2, 2, gzf, 7, gbf, 5);
  setp(3, gv + 0 * NTOK, DH_ / 2, 1, 0, gsf, 8);
  setp(4, gv + 1 * NTOK, DH_ / 2, 1, 0, gbf, 9);
  setp(5, gv + 2 * NTOK, DH_ / 2, 1, 0, gzf, 10);
  setp(6, gq + 0 * (NTOK / 2), DIN_ / 2, 1, 2, gyf, 0);
  setp(7, gq + 1 * (NTOK / 2), DIN_ / 2, 1, 2, gyf, 1);
  setp(8, gq + 2 * (NTOK / 2), DIN_ / 2, 1, 2, gyf, 2);
  proj_mixed<<<dim3(8, 16, 9), 256, GEMM_SMEM>>>(tab);

  // --- 3: V transpose ---
  transpose_v<<<dim3(2, 32, 96), dim3(32, 8)>>>(gv, gvth);

  // --- 4: fused attention ---
  fused_attn<<<dim3(8, 96), 256, FUSED_SMEM>>>(gq, gk, gvth, ba0, ba1, ba2,
                                               scb, gof);

  // --- 5: output projections (f16) ---
  OpTable to{};
  for (int i = 0; i < 3; i++) {
    Op& o = to.op[i];
    o.C = gp + (size_t)i * NTOK; o.K = DH_ / 2; o.nt = 1;
    o.lda = DH_ / 2; o.ldb = DH_ / 2; o.ldc = DH_;
    o.mode = 0;
    o.t[0] = {gof + (size_t)i * (NTOK / 2), WTf(11), C[11]};
  }
  proj_mixed<<<dim3(8, 16, 3), 256, GEMM_SMEM>>>(to);

  // --- 6: residual chain ---
  combine_kernel<<<(int)((NTOK + 255) / 256), 256>>>(
      s, b, z, gp + 0 * NTOK, gp + 1 * NTOK, gp + 2 * NTOK,
      s_out, b_out, z_out);
}

// round 16
// speedup vs baseline: 2.2960x; 1.1153x over previous
#include <cuda_runtime.h>
#include <cuda_fp16.h>
#include <cstdint>
#include <math.h>

// ===========================================================================
// MarkovBlanketAttention on sm_103 — R15: fused_attn widened to 512 threads /
// 256 q-rows per CTA (16 warps/SM for exp/mem/MMA overlap; KV fills halved).
// All-f16 MMA pipeline otherwise identical to the 713.8us R14 winner.
// ===========================================================================

namespace {
constexpr int B_   = 2;
constexpr int S_   = 1024;
constexpr int DIN_ = 512;
constexpr int DH_  = 1024;
constexpr int H_   = 16;
constexpr int HD_  = 64;
constexpr int M_   = B_ * S_;
constexpr size_t NTOK = (size_t)M_ * DH_;
constexpr size_t NSC  = (size_t)B_ * H_ * S_ * S_;
}

// ---- scratch (device globals) ----
__device__ uint32_t g_q[3][NTOK / 2];
__device__ uint32_t g_k[3][NTOK / 2];
__device__ float    g_v[3][NTOK];
__device__ uint32_t g_of[3][NTOK / 2];
__device__ float    g_p[3][NTOK];
__device__ uint32_t g_wtf[12][DH_ * DH_ / 2];
__device__ uint32_t g_vth[96][HD_ * S_ / 2];
__device__ uint32_t g_yfh[M_ * DIN_ / 2];
__device__ uint32_t g_sfh[M_ * DH_ / 2];
__device__ uint32_t g_bfh[M_ * DH_ / 2];
__device__ uint32_t g_zfh[M_ * DH_ / 2];

// ---------------------------------------------------------------------------
// helpers
// ---------------------------------------------------------------------------
__device__ __forceinline__ uint32_t smem_u32(const void* p) {
  uint32_t a;
  asm("{ .reg .u64 t; cvta.to.shared.u64 t, %1; cvt.u32.u64 %0, t; }"
      : "=r"(a) : "l"(p));
  return a;
}
__device__ __forceinline__ void cp16(void* smem, const void* g) {
  asm volatile("cp.async.cg.shared.global [%0], [%1], 16;"
               :: "r"(smem_u32(smem)), "l"(g));
}
__device__ __forceinline__ void cp_commit() {
  asm volatile("cp.async.commit_group;" ::: "memory");
}
template <int N>
__device__ __forceinline__ void cp_wait() {
  asm volatile("cp.async.wait_group %0;" :: "n"(N) : "memory");
}
__device__ __forceinline__ void ldsm4(uint32_t* r, uint32_t addr) {
  asm volatile(
      "ldmatrix.sync.aligned.m8n8.x4.shared.b16 {%0,%1,%2,%3}, [%4];"
      : "=r"(r[0]), "=r"(r[1]), "=r"(r[2]), "=r"(r[3]) : "r"(addr));
}
__device__ __forceinline__ void mma_f16_k16(float* c, const uint32_t* a,
                                            const uint32_t* b) {
  asm volatile(
      "mma.sync.aligned.m16n8k16.row.col.f32.f16.f16.f32 "
      "{%0,%1,%2,%3}, {%4,%5,%6,%7}, {%8,%9}, {%0,%1,%2,%3};"
      : "+f"(c[0]), "+f"(c[1]), "+f"(c[2]), "+f"(c[3])
      : "r"(a[0]), "r"(a[1]), "r"(a[2]), "r"(a[3]), "r"(b[0]), "r"(b[1]));
}
__device__ __forceinline__ uint32_t pack_f16p(float a, float b) {
  __half2 h = __floats2half2_rn(a, b);
  return *(uint32_t*)&h;
}

// ---------------------------------------------------------------------------
// GEMM core (unchanged from R14 winner): BK=32 words, pitch 36, dbl buffer.
// ---------------------------------------------------------------------------
struct Term { const uint32_t* A; const uint32_t* W; const float* bias; };
struct Op   { Term t[3]; float* C; int nt; int K; int lda; int ldb; int ldc;
              int mode; int pad; };
struct OpTable { Op op[9]; };

namespace {
constexpr int GBK = 32;
constexpr int GPITCH = 36;
constexpr int GTILE = 128 * GPITCH;
constexpr int GEMM_SMEM = 4 * GTILE * 4;   // 73728 B
}

template <int BN, bool PACKHALF>
__device__ __forceinline__ void gemm_core(const Op& op, uint32_t* dsm) {
  constexpr int WN = BN / 2;
  constexpr int NT = WN / 8;
  uint32_t* As = dsm;
  uint32_t* Bs = dsm + 2 * GTILE;

  const int t = threadIdx.x;
  const int wid = t >> 5, lane = t & 31;
  const int warp_m = wid & 3;
  const int wn = wid >> 2;
  const int gid = lane >> 2, qid = lane & 3;

  const int bm = blockIdx.y * 128;
  const int bn = blockIdx.x * BN;
  const int cpt = op.K / GBK;
  const int total = op.nt * cpt;

  const uint32_t asb = smem_u32(As);
  const uint32_t bsb = smem_u32(Bs);
  const uint32_t a_off =
      (((lane & 15) * GPITCH) + ((lane >> 4) << 2)) * 4;
  const uint32_t b_off =
      ((((lane & 7) + ((lane >> 4) << 3)) * GPITCH) + (((lane >> 3) & 1) << 2)) * 4;

  float acc[2][NT][4];
#pragma unroll
  for (int mt = 0; mt < 2; mt++)
#pragma unroll
    for (int nt = 0; nt < NT; nt++)
#pragma unroll
      for (int j = 0; j < 4; j++) acc[mt][nt][j] = 0.f;

  auto load_chunk = [&](int c, int buf) {
    const int term = c / cpt;
    const int k0 = (c - term * cpt) * GBK;
    const uint32_t* __restrict__ A = op.t[term].A;
    const uint32_t* __restrict__ W = op.t[term].W;
#pragma unroll
    for (int i = 0; i < 4; i++) {
      int f = t + i * 256;
      int r = f >> 3, c4 = (f & 7) * 4;
      cp16(&As[buf * GTILE + r * GPITCH + c4],
           A + (size_t)(bm + r) * op.lda + k0 + c4);
    }
#pragma unroll
    for (int i = 0; i < BN / 32; i++) {
      int f = t + i * 256;
      int r = f >> 3, c4 = (f & 7) * 4;
      cp16(&Bs[buf * GTILE + r * GPITCH + c4],
           W + (size_t)(bn + r) * op.ldb + k0 + c4);
    }
  };

  load_chunk(0, 0);
  cp_commit();

  for (int c = 0; c < total; c++) {
    const int buf = c & 1;
    if (c + 1 < total) load_chunk(c + 1, (c + 1) & 1);
    cp_commit();
    cp_wait<1>();
    __syncthreads();

#pragma unroll
    for (int kk = 0; kk < GBK; kk += 8) {
      uint32_t af[2][4];
#pragma unroll
      for (int mt = 0; mt < 2; mt++) {
        uint32_t ad = asb + a_off +
            (uint32_t)((buf * GTILE + (warp_m * 32 + mt * 16) * GPITCH + kk) * 4);
        ldsm4(af[mt], ad);
      }
#pragma unroll
      for (int nt2 = 0; nt2 < NT / 2; nt2++) {
        uint32_t bf[4];
        uint32_t bd = bsb + b_off +
            (uint32_t)((buf * GTILE + (wn * WN + nt2 * 16) * GPITCH + kk) * 4);
        ldsm4(bf, bd);
#pragma unroll
        for (int half = 0; half < 2; half++) {
          const int nt = nt2 * 2 + half;
#pragma unroll
          for (int mt = 0; mt < 2; mt++)
            mma_f16_k16(acc[mt][nt], af[mt], bf + half * 2);
        }
      }
    }
    __syncthreads();
  }

#pragma unroll
  for (int mt = 0; mt < 2; mt++) {
    int row0 = bm + warp_m * 32 + mt * 16 + gid;
#pragma unroll
    for (int nt = 0; nt < NT; nt++) {
      int col = bn + wn * WN + nt * 8 + qid * 2;
      float b0 = 0.f, b1 = 0.f;
      if (op.t[0].bias) {
        for (int tt = 0; tt < op.nt; tt++) {
          b0 += op.t[tt].bias[col];
          b1 += op.t[tt].bias[col + 1];
        }
      }
      float v00 = acc[mt][nt][0] + b0, v01 = acc[mt][nt][1] + b1;
      float v10 = acc[mt][nt][2] + b0, v11 = acc[mt][nt][3] + b1;
      if (PACKHALF) {
        uint32_t* Cp = (uint32_t*)op.C;
        int colw = (bn + wn * WN + nt * 8) / 2 + qid;
        Cp[(size_t)row0 * op.ldc + colw]       = pack_f16p(v00, v01);
        Cp[(size_t)(row0 + 8) * op.ldc + colw] = pack_f16p(v10, v11);
      } else {
        *(float2*)(op.C + (size_t)row0 * op.ldc + col) = {v00, v01};
        *(float2*)(op.C + (size_t)(row0 + 8) * op.ldc + col) = {v10, v11};
      }
    }
  }
}

__global__ void __launch_bounds__(256) proj_mixed(const OpTable tab) {
  extern __shared__ uint32_t ds[];
  const Op& op = tab.op[blockIdx.z];
  if (op.mode == 2)
    gemm_core<128, true>(op, ds);
  else
    gemm_core<128, false>(op, ds);
}

// ---------------------------------------------------------------------------
// Fused attention: 512 threads, 256 q-rows per CTA, shared K/VT tiles.
// ---------------------------------------------------------------------------
namespace {
constexpr int QP = 36;                      // Q/K pitch (words)
constexpr int VTP = 68;                     // VT/Ps pitch (words)
constexpr int FQ_W = 256 * QP;              // 9216 (Q tile)
constexpr int FK_W = 128 * QP;              // 4608 (one K tile)
constexpr int FVT_W = 64 * VTP;             // 4352 (one VT tile)
constexpr int FKS_OFF = FQ_W;               // K tiles base
constexpr int FVT_OFF = FQ_W + 2 * FK_W;    // 18432
constexpr int FPS_OFF = FVT_OFF + 2 * FVT_W;// 27136
constexpr int FUSED_SMEM = (FPS_OFF + 256 * VTP) * 4;  // 178176 B
}

__global__ void __launch_bounds__(512) fused_attn(
    const uint32_t* __restrict__ qb, const uint32_t* __restrict__ kb,
    const uint32_t* __restrict__ vtb, const float* __restrict__ bias0,
    const float* __restrict__ bias1, const float* __restrict__ bias2,
    float* __restrict__ score_out, uint32_t* __restrict__ ofb) {
  extern __shared__ uint32_t sm[];
  uint32_t* Qs = sm;                        // [256][QP]
  uint32_t* Ks = sm + FKS_OFF;              // [2][128][QP]
  uint32_t* VT = sm + FVT_OFF;              // [2][64][VTP]
  uint32_t* Ps = sm + FPS_OFF;              // [256][VTP]

  const int zz = blockIdx.y;
  const int st = zz >> 5, bh = zz & 31, b = bh >> 4, h = bh & 15;
  const int q0 = blockIdx.x * 256;

  const uint32_t* qp = qb + (size_t)st * (NTOK / 2) +
                       (size_t)(b * S_ + q0) * (DH_ / 2) + h * (HD_ / 2);
  const uint32_t* kp = kb + (size_t)st * (NTOK / 2) +
                       (size_t)b * S_ * (DH_ / 2) + h * (HD_ / 2);
  const uint32_t* vtp = vtb + (size_t)zz * (HD_ * S_ / 2);
  const float* bias = (st == 0) ? bias0 : (st == 1) ? bias1 : bias2;
  const float* brow = bias + (size_t)bh * S_ * S_ + (size_t)q0 * S_;
  float* srow = score_out + (size_t)st * NSC + (size_t)bh * S_ * S_ + (size_t)q0 * S_;
  uint32_t* ofp = ofb + (size_t)st * (NTOK / 2) +
                  (size_t)(b * S_ + q0) * (DH_ / 2) + h * (HD_ / 2);

  const int t = threadIdx.x;
  const int w = t >> 5, lane = t & 31;
  const int gid = lane >> 2, qid = lane & 3;
  const int r0 = w * 16 + gid;              // 0..255

  const uint32_t smb = smem_u32(sm);
  const uint32_t a36 =
      (((lane & 15) * QP) + ((lane >> 4) << 2)) * 4;
  const uint32_t b36 =
      ((((lane & 7) + ((lane >> 4) << 3)) * QP) + (((lane >> 3) & 1) << 2)) * 4;
  const uint32_t a68 =
      (((lane & 15) * VTP) + ((lane >> 4) << 2)) * 4;
  const uint32_t b68 =
      ((((lane & 7) + ((lane >> 4) << 3)) * VTP) + (((lane >> 3) & 1) << 2)) * 4;

  auto load_q = [&]() {
#pragma unroll
    for (int i = 0; i < 4; i++) {           // 256 rows x 32 words
      int f = t + i * 512;
      int r = f >> 3, c4 = (f & 7) * 4;
      cp16(&Qs[r * QP + c4], qp + (size_t)r * (DH_ / 2) + c4);
    }
  };
  auto load_kv = [&](int kbk, int buf) {
#pragma unroll
    for (int i = 0; i < 2; i++) {           // K tile: 128 x 32 words
      int f = t + i * 512;
      int r = f >> 3, c4 = (f & 7) * 4;
      cp16(&Ks[buf * FK_W + r * QP + c4],
           kp + (size_t)(kbk * 128 + r) * (DH_ / 2) + c4);
    }
#pragma unroll
    for (int i = 0; i < 2; i++) {           // VT tile: 64 rows x 64 words
      int f = t + i * 512;
      int r = f >> 4, c4 = (f & 15) * 4;
      cp16(&VT[buf * FVT_W + r * VTP + c4],
           vtp + (size_t)r * (S_ / 2) + kbk * 64 + c4);
    }
  };

  load_q();
  load_kv(0, 0);
  cp_commit();
  load_kv(1, 1);
  cp_commit();

  float m0 = -1e30f, m1 = -1e30f, l0 = 0.f, l1 = 0.f;
  float oacc[8][4];
#pragma unroll
  for (int j = 0; j < 8; j++)
#pragma unroll
    for (int q = 0; q < 4; q++) oacc[j][q] = 0.f;

  const uint32_t q_base = smb + a36 + (uint32_t)(w * 16 * QP * 4);
  const uint32_t p_base = smb + a68 + (uint32_t)((FPS_OFF + w * 16 * VTP) * 4);

  for (int it = 0; it < 8; it++) {
    const int buf = it & 1;
    cp_wait<1>();
    __syncthreads();

    // ---- scores: f16 single MMA ----
    float acc[16][4];
#pragma unroll
    for (int nt = 0; nt < 16; nt++)
#pragma unroll
      for (int q = 0; q < 4; q++) acc[nt][q] = 0.f;

#pragma unroll
    for (int kk = 0; kk < 32; kk += 8) {
      uint32_t af[4];
      ldsm4(af, q_base + (uint32_t)(kk * 4));
#pragma unroll
      for (int nt2 = 0; nt2 < 8; nt2++) {
        uint32_t kf[4];
        uint32_t kd = smb + b36 +
            (uint32_t)((FKS_OFF + buf * FK_W + nt2 * 16 * QP + kk) * 4);
        ldsm4(kf, kd);
        mma_f16_k16(acc[nt2 * 2],     af, kf);
        mma_f16_k16(acc[nt2 * 2 + 1], af, kf + 2);
      }
    }

    // ---- raw scores out, add bias ----
    const int cbase = it * 128;
#pragma unroll
    for (int nt = 0; nt < 16; nt++) {
      int col = cbase + nt * 8 + qid * 2;
      *(float2*)(srow + (size_t)(r0)     * S_ + col) = {acc[nt][0], acc[nt][1]};
      *(float2*)(srow + (size_t)(r0 + 8) * S_ + col) = {acc[nt][2], acc[nt][3]};
      float2 bv0 = *(const float2*)(brow + (size_t)(r0)     * S_ + col);
      float2 bv1 = *(const float2*)(brow + (size_t)(r0 + 8) * S_ + col);
      acc[nt][0] += bv0.x; acc[nt][1] += bv0.y;
      acc[nt][2] += bv1.x; acc[nt][3] += bv1.y;
    }

    // ---- online softmax ----
    float mt0 = -1e30f, mt1 = -1e30f;
#pragma unroll
    for (int nt = 0; nt < 16; nt++) {
      mt0 = fmaxf(mt0, fmaxf(acc[nt][0], acc[nt][1]));
      mt1 = fmaxf(mt1, fmaxf(acc[nt][2], acc[nt][3]));
    }
    mt0 = fmaxf(mt0, __shfl_xor_sync(0xffffffffu, mt0, 1));
    mt0 = fmaxf(mt0, __shfl_xor_sync(0xffffffffu, mt0, 2));
    mt1 = fmaxf(mt1, __shfl_xor_sync(0xffffffffu, mt1, 1));
    mt1 = fmaxf(mt1, __shfl_xor_sync(0xffffffffu, mt1, 2));

    float m0n = fmaxf(m0, mt0), m1n = fmaxf(m1, mt1);
    float sc0 = __expf(m0 - m0n), sc1 = __expf(m1 - m1n);
    m0 = m0n; m1 = m1n;
    l0 *= sc0; l1 *= sc1;
#pragma unroll
    for (int j = 0; j < 8; j++) {
      oacc[j][0] *= sc0; oacc[j][1] *= sc0;
      oacc[j][2] *= sc1; oacc[j][3] *= sc1;
    }

    float ts0 = 0.f, ts1 = 0.f;
#pragma unroll
    for (int nt = 0; nt < 16; nt++) {
      float p00 = __expf(acc[nt][0] - m0);
      float p01 = __expf(acc[nt][1] - m0);
      float p10 = __expf(acc[nt][2] - m1);
      float p11 = __expf(acc[nt][3] - m1);
      ts0 += p00 + p01; ts1 += p10 + p11;
      Ps[(r0)     * VTP + nt * 4 + qid] = pack_f16p(p00, p01);
      Ps[(r0 + 8) * VTP + nt * 4 + qid] = pack_f16p(p10, p11);
    }
    ts0 += __shfl_xor_sync(0xffffffffu, ts0, 1);
    ts0 += __shfl_xor_sync(0xffffffffu, ts0, 2);
    ts1 += __shfl_xor_sync(0xffffffffu, ts1, 1);
    ts1 += __shfl_xor_sync(0xffffffffu, ts1, 2);
    l0 += ts0; l1 += ts1;
    __syncwarp();

    // ---- PV ----
#pragma unroll
    for (int kw = 0; kw < 64; kw += 8) {
      uint32_t ap[4];
      ldsm4(ap, p_base + (uint32_t)(kw * 4));
#pragma unroll
      for (int j2 = 0; j2 < 4; j2++) {
        uint32_t vf[4];
        uint32_t vd = smb + b68 +
            (uint32_t)((FVT_OFF + buf * FVT_W + j2 * 16 * VTP + kw) * 4);
        ldsm4(vf, vd);
        mma_f16_k16(oacc[j2 * 2],     ap, vf);
        mma_f16_k16(oacc[j2 * 2 + 1], ap, vf + 2);
      }
    }
    __syncthreads();

    if (it + 2 < 8) load_kv(it + 2, buf);
    cp_commit();
  }

  float inv0 = 1.f / l0, inv1 = 1.f / l1;
#pragma unroll
  for (int j = 0; j < 8; j++) {
    int cw = j * 4 + qid;
    ofp[(size_t)(r0)     * (DH_ / 2) + cw] =
        pack_f16p(oacc[j][0] * inv0, oacc[j][1] * inv0);
    ofp[(size_t)(r0 + 8) * (DH_ / 2) + cw] =
        pack_f16p(oacc[j][2] * inv1, oacc[j][3] * inv1);
  }
}

// ---- input packing ----
__global__ void __launch_bounds__(256) pack_all(
    const float* __restrict__ y, const float* __restrict__ s,
    const float* __restrict__ b, const float* __restrict__ z,
    uint32_t* __restrict__ yfh, uint32_t* __restrict__ sfh,
    uint32_t* __restrict__ bfh, uint32_t* __restrict__ zfh) {
  const int which = blockIdx.y;
  const int i2 = blockIdx.x * 256 + threadIdx.x;
  const float* src; uint32_t* dst; int npair;
  switch (which) {
    case 0: src = y; dst = yfh; npair = M_ * DIN_ / 2; break;
    case 1: src = s; dst = sfh; npair = M_ * DH_ / 2; break;
    case 2: src = b; dst = bfh; npair = M_ * DH_ / 2; break;
    default: src = z; dst = zfh; npair = M_ * DH_ / 2; break;
  }
  if (i2 >= npair) return;
  float2 v = *(const float2*)(src + 2 * i2);
  dst[i2] = pack_f16p(v.x, v.y);
}

// ---- weight transpose ----
struct WEnt { const float* src; uint32_t* dst; int K; };
struct WTab { WEnt e[12]; };

__global__ void __launch_bounds__(256) transpose_w(const WTab tab) {
  WEnt e = tab.e[blockIdx.z];
  int n0 = blockIdx.x * 32, k0 = blockIdx.y * 32;
  if (k0 >= e.K) return;
  __shared__ float tl[32][33];
  int tx = threadIdx.x, ty = threadIdx.y;
#pragma unroll
  for (int i = 0; i < 32; i += 8)
    tl[ty + i][tx] = e.src[(size_t)(k0 + ty + i) * DH_ + n0 + tx];
  __syncthreads();
  if (tx < 16) {
#pragma unroll
    for (int i = 0; i < 32; i += 8) {
      int nn = ty + i;
      e.dst[(size_t)(n0 + nn) * (e.K / 2) + k0 / 2 + tx] =
          pack_f16p(tl[2 * tx][nn], tl[2 * tx + 1][nn]);
    }
  }
}

// ---- V transpose ----
__global__ void __launch_bounds__(256) transpose_v(const float* __restrict__ v,
                                                   uint32_t* __restrict__ vt) {
  int z = blockIdx.z, st = z >> 5, bh = z & 31, b = bh >> 4, h = bh & 15;
  int c0 = blockIdx.x * 32, k0 = blockIdx.y * 32;
  __shared__ float tl[32][33];
  int tx = threadIdx.x, ty = threadIdx.y;
  const float* src = v + (size_t)st * NTOK + (size_t)b * S_ * DH_ + h * HD_;
  uint32_t* dst = vt + (size_t)z * (HD_ * S_ / 2);
#pragma unroll
  for (int i = 0; i < 32; i += 8)
    tl[ty + i][tx] = src[(size_t)(k0 + ty + i) * DH_ + c0 + tx];
  __syncthreads();
  if (tx < 16) {
#pragma unroll
    for (int i = 0; i < 32; i += 8) {
      int cc = ty + i;
      dst[(size_t)(c0 + cc) * (S_ / 2) + k0 / 2 + tx] =
          pack_f16p(tl[2 * tx][cc], tl[2 * tx + 1][cc]);
    }
  }
}

// ---- residual chain ----
__global__ void __launch_bounds__(256) combine_kernel(
    const float* __restrict__ s, const float* __restrict__ b,
    const float* __restrict__ z, const float* __restrict__ ps,
    const float* __restrict__ pb, const float* __restrict__ pz,
    float* __restrict__ os, float* __restrict__ ob, float* __restrict__ oz) {
  size_t i = (size_t)blockIdx.x * 256 + threadIdx.x;
  if (i >= NTOK) return;
  float so = s[i] + ps[i];
  float bo = so + b[i] + pb[i];
  float zo = bo + z[i] + pz[i];
  os[i] = so; ob[i] = bo; oz[i] = zo;
}

// ===========================================================================
extern "C" void kernel_launch(void* const* d_in, const int* in_sizes, int n_in,
                              void* d_out, int out_size) {
  const float* y    = (const float*)d_in[0];
  const float* s    = (const float*)d_in[1];
  const float* b    = (const float*)d_in[2];
  const float* z    = (const float*)d_in[3];
  const float* ba0  = (const float*)d_in[4];
  const float* ba1  = (const float*)d_in[5];
  const float* ba2  = (const float*)d_in[6];
  const float* W[12] = {
      (const float*)d_in[7],  (const float*)d_in[9],  (const float*)d_in[11],
      (const float*)d_in[13], (const float*)d_in[15], (const float*)d_in[17],
      (const float*)d_in[19], (const float*)d_in[21],
      (const float*)d_in[23], (const float*)d_in[25], (const float*)d_in[27],
      (const float*)d_in[29]};
  const float* C[12] = {
      (const float*)d_in[8],  (const float*)d_in[10], (const float*)d_in[12],
      (const float*)d_in[14], (const float*)d_in[16], (const float*)d_in[18],
      (const float*)d_in[20], (const float*)d_in[22],
      (const float*)d_in[24], (const float*)d_in[26], (const float*)d_in[28],
      (const float*)d_in[30]};
  const int KW[12] = {DIN_, DIN_, DIN_, DH_, DH_, DH_, DH_, DH_,
                      DH_, DH_, DH_, DH_};

  float* out   = (float*)d_out;
  float* s_out = out;
  float* b_out = out + NTOK;
  float* z_out = out + 2 * NTOK;
  float* scb   = out + 3 * NTOK;

  uint32_t *gq, *gk, *gof, *gwtf, *gvth, *gyf, *gsf, *gbf, *gzf;
  float *gv, *gp;
  cudaGetSymbolAddress((void**)&gq, g_q);
  cudaGetSymbolAddress((void**)&gk, g_k);
  cudaGetSymbolAddress((void**)&gv, g_v);
  cudaGetSymbolAddress((void**)&gof, g_of);
  cudaGetSymbolAddress((void**)&gp, g_p);
  cudaGetSymbolAddress((void**)&gwtf, g_wtf);
  cudaGetSymbolAddress((void**)&gvth, g_vth);
  cudaGetSymbolAddress((void**)&gyf, g_yfh);
  cudaGetSymbolAddress((void**)&gsf, g_sfh);
  cudaGetSymbolAddress((void**)&gbf, g_bfh);
  cudaGetSymbolAddress((void**)&gzf, g_zfh);

  cudaFuncSetAttribute(fused_attn, cudaFuncAttributeMaxDynamicSharedMemorySize,
                       FUSED_SMEM);
  cudaFuncSetAttribute(proj_mixed, cudaFuncAttributeMaxDynamicSharedMemorySize,
                       GEMM_SMEM);

  // --- 1a: pack all inputs to f16 pairs ---
  pack_all<<<dim3(4096, 4), 256>>>(y, s, b, z, gyf, gsf, gbf, gzf);

  // --- 1b: transpose all weights to f16 pairs ---
  WTab wt{};
  for (int i = 0; i < 12; i++)
    wt.e[i] = {W[i], gwtf + (size_t)i * (DH_ * DH_ / 2), KW[i]};
  transpose_w<<<dim3(32, 32, 12), dim3(32, 8)>>>(wt);

  auto WTf = [&](int i) -> const uint32_t* {
    return gwtf + (size_t)i * (DH_ * DH_ / 2);
  };

  // --- 2: ALL 9 projection ops in ONE launch (heavy first) ---
  OpTable tab{};
  auto setp = [&](int idx, void* Cp, int Kw, int nt, int mode,
                  const uint32_t* A0, int w0,
                  const uint32_t* A1 = nullptr, int w1 = -1,
                  const uint32_t* A2 = nullptr, int w2 = -1) {
    Op& o = tab.op[idx];
    o.C = (float*)Cp; o.K = Kw; o.nt = nt; o.lda = Kw; o.ldb = Kw;
    o.ldc = (mode == 2) ? DH_ / 2 : DH_;
    o.mode = mode;
    o.t[0] = {A0, WTf(w0), C[w0]};
    if (nt > 1) o.t[1] = {A1, WTf(w1), C[w1]};
    if (nt > 2) o.t[2] = {A2, WTf(w2), C[w2]};
  };
  setp(0, gk + 1 * (NTOK / 2), DH_ / 2, 3, 2, gbf, 6, gsf, 4, gzf, 5);
  setp(1, gk + 0 * (NTOK / 2), DH_ / 2, 2, 2, gsf, 3, gbf, 4);
  setp(2, gk + 2 * (NTOK / 2), DH_ / 2, 2, 2, gzf, 7, gbf, 5);
  setp(3, gv + 0 * NTOK, DH_ / 2, 1, 0, gsf, 8);
  setp(4, gv + 1 * NTOK, DH_ / 2, 1, 0, gbf, 9);
  setp(5, gv + 2 * NTOK, DH_ / 2, 1, 0, gzf, 10);
  setp(6, gq + 0 * (NTOK / 2), DIN_ / 2, 1, 2, gyf, 0);
  setp(7, gq + 1 * (NTOK / 2), DIN_ / 2, 1, 2, gyf, 1);
  setp(8, gq + 2 * (NTOK / 2), DIN_ / 2, 1, 2, gyf, 2);
  proj_mixed<<<dim3(8, 16, 9), 256, GEMM_SMEM>>>(tab);

  // --- 3: V transpose ---
  transpose_v<<<dim3(2, 32, 96), dim3(32, 8)>>>(gv, gvth);

  // --- 4: fused attention (512 threads, 256 q-rows per CTA) ---
  fused_attn<<<dim3(S_ / 256, 96), 512, FUSED_SMEM>>>(gq, gk, gvth,
                                                      ba0, ba1, ba2, scb, gof);

  // --- 5: output projections (f16) ---
  OpTable to{};
  for (int i = 0; i < 3; i++) {
    Op& o = to.op[i];
    o.C = gp + (size_t)i * NTOK; o.K = DH_ / 2; o.nt = 1;
    o.lda = DH_ / 2; o.ldb = DH_ / 2; o.ldc = DH_;
    o.mode = 0;
    o.t[0] = {gof + (size_t)i * (NTOK / 2), WTf(11), C[11]};
  }
  proj_mixed<<<dim3(8, 16, 3), 256, GEMM_SMEM>>>(to);

  // --- 6: residual chain ---
  combine_kernel<<<(int)((NTOK + 255) / 256), 256>>>(
      s, b, z, gp + 0 * NTOK, gp + 1 * NTOK, gp + 2 * NTOK,
      s_out, b_out, z_out);
}

// round 17
// speedup vs baseline: 2.3377x; 1.0182x over previous
#include <cuda_runtime.h>
#include <cuda_fp16.h>
#include <cstdint>
#include <math.h>

// ===========================================================================
// MarkovBlanketAttention on sm_103 — R16: FA2-style register reuse in
// fused_attn (P stays in registers: score C-fragment == PV A-fragment after
// f16x2 packing). Ps smem region deleted (178KB -> 106KB). Rest = R16 winner.
// ===========================================================================

namespace {
constexpr int B_   = 2;
constexpr int S_   = 1024;
constexpr int DIN_ = 512;
constexpr int DH_  = 1024;
constexpr int H_   = 16;
constexpr int HD_  = 64;
constexpr int M_   = B_ * S_;
constexpr size_t NTOK = (size_t)M_ * DH_;
constexpr size_t NSC  = (size_t)B_ * H_ * S_ * S_;
}

// ---- scratch (device globals) ----
__device__ uint32_t g_q[3][NTOK / 2];
__device__ uint32_t g_k[3][NTOK / 2];
__device__ float    g_v[3][NTOK];
__device__ uint32_t g_of[3][NTOK / 2];
__device__ float    g_p[3][NTOK];
__device__ uint32_t g_wtf[12][DH_ * DH_ / 2];
__device__ uint32_t g_vth[96][HD_ * S_ / 2];
__device__ uint32_t g_yfh[M_ * DIN_ / 2];
__device__ uint32_t g_sfh[M_ * DH_ / 2];
__device__ uint32_t g_bfh[M_ * DH_ / 2];
__device__ uint32_t g_zfh[M_ * DH_ / 2];

// ---------------------------------------------------------------------------
// helpers
// ---------------------------------------------------------------------------
__device__ __forceinline__ uint32_t smem_u32(const void* p) {
  uint32_t a;
  asm("{ .reg .u64 t; cvta.to.shared.u64 t, %1; cvt.u32.u64 %0, t; }"
      : "=r"(a) : "l"(p));
  return a;
}
__device__ __forceinline__ void cp16(void* smem, const void* g) {
  asm volatile("cp.async.cg.shared.global [%0], [%1], 16;"
               :: "r"(smem_u32(smem)), "l"(g));
}
__device__ __forceinline__ void cp_commit() {
  asm volatile("cp.async.commit_group;" ::: "memory");
}
template <int N>
__device__ __forceinline__ void cp_wait() {
  asm volatile("cp.async.wait_group %0;" :: "n"(N) : "memory");
}
__device__ __forceinline__ void ldsm4(uint32_t* r, uint32_t addr) {
  asm volatile(
      "ldmatrix.sync.aligned.m8n8.x4.shared.b16 {%0,%1,%2,%3}, [%4];"
      : "=r"(r[0]), "=r"(r[1]), "=r"(r[2]), "=r"(r[3]) : "r"(addr));
}
__device__ __forceinline__ void mma_f16_k16(float* c, const uint32_t* a,
                                            const uint32_t* b) {
  asm volatile(
      "mma.sync.aligned.m16n8k16.row.col.f32.f16.f16.f32 "
      "{%0,%1,%2,%3}, {%4,%5,%6,%7}, {%8,%9}, {%0,%1,%2,%3};"
      : "+f"(c[0]), "+f"(c[1]), "+f"(c[2]), "+f"(c[3])
      : "r"(a[0]), "r"(a[1]), "r"(a[2]), "r"(a[3]), "r"(b[0]), "r"(b[1]));
}
__device__ __forceinline__ uint32_t pack_f16p(float a, float b) {
  __half2 h = __floats2half2_rn(a, b);
  return *(uint32_t*)&h;
}

// ---------------------------------------------------------------------------
// GEMM core (unchanged): BK=32 words, pitch 36, double buffer, f16 MMA.
// ---------------------------------------------------------------------------
struct Term { const uint32_t* A; const uint32_t* W; const float* bias; };
struct Op   { Term t[3]; float* C; int nt; int K; int lda; int ldb; int ldc;
              int mode; int pad; };
struct OpTable { Op op[9]; };

namespace {
constexpr int GBK = 32;
constexpr int GPITCH = 36;
constexpr int GTILE = 128 * GPITCH;
constexpr int GEMM_SMEM = 4 * GTILE * 4;   // 73728 B
}

template <int BN, bool PACKHALF>
__device__ __forceinline__ void gemm_core(const Op& op, uint32_t* dsm) {
  constexpr int WN = BN / 2;
  constexpr int NT = WN / 8;
  uint32_t* As = dsm;
  uint32_t* Bs = dsm + 2 * GTILE;

  const int t = threadIdx.x;
  const int wid = t >> 5, lane = t & 31;
  const int warp_m = wid & 3;
  const int wn = wid >> 2;
  const int gid = lane >> 2, qid = lane & 3;

  const int bm = blockIdx.y * 128;
  const int bn = blockIdx.x * BN;
  const int cpt = op.K / GBK;
  const int total = op.nt * cpt;

  const uint32_t asb = smem_u32(As);
  const uint32_t bsb = smem_u32(Bs);
  const uint32_t a_off =
      (((lane & 15) * GPITCH) + ((lane >> 4) << 2)) * 4;
  const uint32_t b_off =
      ((((lane & 7) + ((lane >> 4) << 3)) * GPITCH) + (((lane >> 3) & 1) << 2)) * 4;

  float acc[2][NT][4];
#pragma unroll
  for (int mt = 0; mt < 2; mt++)
#pragma unroll
    for (int nt = 0; nt < NT; nt++)
#pragma unroll
      for (int j = 0; j < 4; j++) acc[mt][nt][j] = 0.f;

  auto load_chunk = [&](int c, int buf) {
    const int term = c / cpt;
    const int k0 = (c - term * cpt) * GBK;
    const uint32_t* __restrict__ A = op.t[term].A;
    const uint32_t* __restrict__ W = op.t[term].W;
#pragma unroll
    for (int i = 0; i < 4; i++) {
      int f = t + i * 256;
      int r = f >> 3, c4 = (f & 7) * 4;
      cp16(&As[buf * GTILE + r * GPITCH + c4],
           A + (size_t)(bm + r) * op.lda + k0 + c4);
    }
#pragma unroll
    for (int i = 0; i < BN / 32; i++) {
      int f = t + i * 256;
      int r = f >> 3, c4 = (f & 7) * 4;
      cp16(&Bs[buf * GTILE + r * GPITCH + c4],
           W + (size_t)(bn + r) * op.ldb + k0 + c4);
    }
  };

  load_chunk(0, 0);
  cp_commit();

  for (int c = 0; c < total; c++) {
    const int buf = c & 1;
    if (c + 1 < total) load_chunk(c + 1, (c + 1) & 1);
    cp_commit();
    cp_wait<1>();
    __syncthreads();

#pragma unroll
    for (int kk = 0; kk < GBK; kk += 8) {
      uint32_t af[2][4];
#pragma unroll
      for (int mt = 0; mt < 2; mt++) {
        uint32_t ad = asb + a_off +
            (uint32_t)((buf * GTILE + (warp_m * 32 + mt * 16) * GPITCH + kk) * 4);
        ldsm4(af[mt], ad);
      }
#pragma unroll
      for (int nt2 = 0; nt2 < NT / 2; nt2++) {
        uint32_t bf[4];
        uint32_t bd = bsb + b_off +
            (uint32_t)((buf * GTILE + (wn * WN + nt2 * 16) * GPITCH + kk) * 4);
        ldsm4(bf, bd);
#pragma unroll
        for (int half = 0; half < 2; half++) {
          const int nt = nt2 * 2 + half;
#pragma unroll
          for (int mt = 0; mt < 2; mt++)
            mma_f16_k16(acc[mt][nt], af[mt], bf + half * 2);
        }
      }
    }
    __syncthreads();
  }

#pragma unroll
  for (int mt = 0; mt < 2; mt++) {
    int row0 = bm + warp_m * 32 + mt * 16 + gid;
#pragma unroll
    for (int nt = 0; nt < NT; nt++) {
      int col = bn + wn * WN + nt * 8 + qid * 2;
      float b0 = 0.f, b1 = 0.f;
      if (op.t[0].bias) {
        for (int tt = 0; tt < op.nt; tt++) {
          b0 += op.t[tt].bias[col];
          b1 += op.t[tt].bias[col + 1];
        }
      }
      float v00 = acc[mt][nt][0] + b0, v01 = acc[mt][nt][1] + b1;
      float v10 = acc[mt][nt][2] + b0, v11 = acc[mt][nt][3] + b1;
      if (PACKHALF) {
        uint32_t* Cp = (uint32_t*)op.C;
        int colw = (bn + wn * WN + nt * 8) / 2 + qid;
        Cp[(size_t)row0 * op.ldc + colw]       = pack_f16p(v00, v01);
        Cp[(size_t)(row0 + 8) * op.ldc + colw] = pack_f16p(v10, v11);
      } else {
        *(float2*)(op.C + (size_t)row0 * op.ldc + col) = {v00, v01};
        *(float2*)(op.C + (size_t)(row0 + 8) * op.ldc + col) = {v10, v11};
      }
    }
  }
}

__global__ void __launch_bounds__(256) proj_mixed(const OpTable tab) {
  extern __shared__ uint32_t ds[];
  const Op& op = tab.op[blockIdx.z];
  if (op.mode == 2)
    gemm_core<128, true>(op, ds);
  else
    gemm_core<128, false>(op, ds);
}

// ---------------------------------------------------------------------------
// Fused attention: 512 threads, 256 q-rows per CTA; P held in registers
// (FA2 fragment reuse), no Ps smem.
// ---------------------------------------------------------------------------
namespace {
constexpr int QP = 36;                      // Q/K pitch (words)
constexpr int VTP = 68;                     // VT pitch (words)
constexpr int FQ_W = 256 * QP;              // 9216 (Q tile)
constexpr int FK_W = 128 * QP;              // 4608 (one K tile)
constexpr int FVT_W = 64 * VTP;             // 4352 (one VT tile)
constexpr int FKS_OFF = FQ_W;
constexpr int FVT_OFF = FQ_W + 2 * FK_W;    // 18432
constexpr int FUSED_SMEM = (FVT_OFF + 2 * FVT_W) * 4;  // 108544 B
}

__global__ void __launch_bounds__(512) fused_attn(
    const uint32_t* __restrict__ qb, const uint32_t* __restrict__ kb,
    const uint32_t* __restrict__ vtb, const float* __restrict__ bias0,
    const float* __restrict__ bias1, const float* __restrict__ bias2,
    float* __restrict__ score_out, uint32_t* __restrict__ ofb) {
  extern __shared__ uint32_t sm[];
  uint32_t* Qs = sm;                        // [256][QP]
  uint32_t* Ks = sm + FKS_OFF;              // [2][128][QP]
  uint32_t* VT = sm + FVT_OFF;              // [2][64][VTP]

  const int zz = blockIdx.y;
  const int st = zz >> 5, bh = zz & 31, b = bh >> 4, h = bh & 15;
  const int q0 = blockIdx.x * 256;

  const uint32_t* qp = qb + (size_t)st * (NTOK / 2) +
                       (size_t)(b * S_ + q0) * (DH_ / 2) + h * (HD_ / 2);
  const uint32_t* kp = kb + (size_t)st * (NTOK / 2) +
                       (size_t)b * S_ * (DH_ / 2) + h * (HD_ / 2);
  const uint32_t* vtp = vtb + (size_t)zz * (HD_ * S_ / 2);
  const float* bias = (st == 0) ? bias0 : (st == 1) ? bias1 : bias2;
  const float* brow = bias + (size_t)bh * S_ * S_ + (size_t)q0 * S_;
  float* srow = score_out + (size_t)st * NSC + (size_t)bh * S_ * S_ + (size_t)q0 * S_;
  uint32_t* ofp = ofb + (size_t)st * (NTOK / 2) +
                  (size_t)(b * S_ + q0) * (DH_ / 2) + h * (HD_ / 2);

  const int t = threadIdx.x;
  const int w = t >> 5, lane = t & 31;
  const int gid = lane >> 2, qid = lane & 3;
  const int r0 = w * 16 + gid;              // 0..255

  const uint32_t smb = smem_u32(sm);
  const uint32_t a36 =
      (((lane & 15) * QP) + ((lane >> 4) << 2)) * 4;
  const uint32_t b36 =
      ((((lane & 7) + ((lane >> 4) << 3)) * QP) + (((lane >> 3) & 1) << 2)) * 4;
  const uint32_t b68 =
      ((((lane & 7) + ((lane >> 4) << 3)) * VTP) + (((lane >> 3) & 1) << 2)) * 4;

  auto load_q = [&]() {
#pragma unroll
    for (int i = 0; i < 4; i++) {           // 256 rows x 32 words
      int f = t + i * 512;
      int r = f >> 3, c4 = (f & 7) * 4;
      cp16(&Qs[r * QP + c4], qp + (size_t)r * (DH_ / 2) + c4);
    }
  };
  auto load_kv = [&](int kbk, int buf) {
#pragma unroll
    for (int i = 0; i < 2; i++) {           // K tile: 128 x 32 words
      int f = t + i * 512;
      int r = f >> 3, c4 = (f & 7) * 4;
      cp16(&Ks[buf * FK_W + r * QP + c4],
           kp + (size_t)(kbk * 128 + r) * (DH_ / 2) + c4);
    }
#pragma unroll
    for (int i = 0; i < 2; i++) {           // VT tile: 64 rows x 64 words
      int f = t + i * 512;
      int r = f >> 4, c4 = (f & 15) * 4;
      cp16(&VT[buf * FVT_W + r * VTP + c4],
           vtp + (size_t)r * (S_ / 2) + kbk * 64 + c4);
    }
  };

  load_q();
  load_kv(0, 0);
  cp_commit();
  load_kv(1, 1);
  cp_commit();

  float m0 = -1e30f, m1 = -1e30f, l0 = 0.f, l1 = 0.f;
  float oacc[8][4];
#pragma unroll
  for (int j = 0; j < 8; j++)
#pragma unroll
    for (int q = 0; q < 4; q++) oacc[j][q] = 0.f;

  const uint32_t q_base = smb + a36 + (uint32_t)(w * 16 * QP * 4);

  for (int it = 0; it < 8; it++) {
    const int buf = it & 1;
    cp_wait<1>();
    __syncthreads();

    // ---- scores: f16 single MMA ----
    float acc[16][4];
#pragma unroll
    for (int nt = 0; nt < 16; nt++)
#pragma unroll
      for (int q = 0; q < 4; q++) acc[nt][q] = 0.f;

#pragma unroll
    for (int kk = 0; kk < 32; kk += 8) {
      uint32_t af[4];
      ldsm4(af, q_base + (uint32_t)(kk * 4));
#pragma unroll
      for (int nt2 = 0; nt2 < 8; nt2++) {
        uint32_t kf[4];
        uint32_t kd = smb + b36 +
            (uint32_t)((FKS_OFF + buf * FK_W + nt2 * 16 * QP + kk) * 4);
        ldsm4(kf, kd);
        mma_f16_k16(acc[nt2 * 2],     af, kf);
        mma_f16_k16(acc[nt2 * 2 + 1], af, kf + 2);
      }
    }

    // ---- raw scores out, add bias ----
    const int cbase = it * 128;
#pragma unroll
    for (int nt = 0; nt < 16; nt++) {
      int col = cbase + nt * 8 + qid * 2;
      *(float2*)(srow + (size_t)(r0)     * S_ + col) = {acc[nt][0], acc[nt][1]};
      *(float2*)(srow + (size_t)(r0 + 8) * S_ + col) = {acc[nt][2], acc[nt][3]};
      float2 bv0 = *(const float2*)(brow + (size_t)(r0)     * S_ + col);
      float2 bv1 = *(const float2*)(brow + (size_t)(r0 + 8) * S_ + col);
      acc[nt][0] += bv0.x; acc[nt][1] += bv0.y;
      acc[nt][2] += bv1.x; acc[nt][3] += bv1.y;
    }

    // ---- online softmax ----
    float mt0 = -1e30f, mt1 = -1e30f;
#pragma unroll
    for (int nt = 0; nt < 16; nt++) {
      mt0 = fmaxf(mt0, fmaxf(acc[nt][0], acc[nt][1]));
      mt1 = fmaxf(mt1, fmaxf(acc[nt][2], acc[nt][3]));
    }
    mt0 = fmaxf(mt0, __shfl_xor_sync(0xffffffffu, mt0, 1));
    mt0 = fmaxf(mt0, __shfl_xor_sync(0xffffffffu, mt0, 2));
    mt1 = fmaxf(mt1, __shfl_xor_sync(0xffffffffu, mt1, 1));
    mt1 = fmaxf(mt1, __shfl_xor_sync(0xffffffffu, mt1, 2));

    float m0n = fmaxf(m0, mt0), m1n = fmaxf(m1, mt1);
    float sc0 = __expf(m0 - m0n), sc1 = __expf(m1 - m1n);
    m0 = m0n; m1 = m1n;
    l0 *= sc0; l1 *= sc1;
#pragma unroll
    for (int j = 0; j < 8; j++) {
      oacc[j][0] *= sc0; oacc[j][1] *= sc0;
      oacc[j][2] *= sc1; oacc[j][3] *= sc1;
    }

    // ---- exp in place (P stays in registers) ----
    float ts0 = 0.f, ts1 = 0.f;
#pragma unroll
    for (int nt = 0; nt < 16; nt++) {
      acc[nt][0] = __expf(acc[nt][0] - m0);
      acc[nt][1] = __expf(acc[nt][1] - m0);
      acc[nt][2] = __expf(acc[nt][2] - m1);
      acc[nt][3] = __expf(acc[nt][3] - m1);
      ts0 += acc[nt][0] + acc[nt][1];
      ts1 += acc[nt][2] + acc[nt][3];
    }
    ts0 += __shfl_xor_sync(0xffffffffu, ts0, 1);
    ts0 += __shfl_xor_sync(0xffffffffu, ts0, 2);
    ts1 += __shfl_xor_sync(0xffffffffu, ts1, 1);
    ts1 += __shfl_xor_sync(0xffffffffu, ts1, 2);
    l0 += ts0; l1 += ts1;

    // ---- PV: C-fragment -> A-fragment register reuse ----
#pragma unroll
    for (int j = 0; j < 8; j++) {           // k-chunk = 16 tokens
      uint32_t ap[4];
      ap[0] = pack_f16p(acc[2 * j][0],     acc[2 * j][1]);
      ap[1] = pack_f16p(acc[2 * j][2],     acc[2 * j][3]);
      ap[2] = pack_f16p(acc[2 * j + 1][0], acc[2 * j + 1][1]);
      ap[3] = pack_f16p(acc[2 * j + 1][2], acc[2 * j + 1][3]);
#pragma unroll
      for (int j2 = 0; j2 < 4; j2++) {
        uint32_t vf[4];
        uint32_t vd = smb + b68 +
            (uint32_t)((FVT_OFF + buf * FVT_W + j2 * 16 * VTP + j * 8) * 4);
        ldsm4(vf, vd);
        mma_f16_k16(oacc[j2 * 2],     ap, vf);
        mma_f16_k16(oacc[j2 * 2 + 1], ap, vf + 2);
      }
    }
    __syncthreads();

    if (it + 2 < 8) load_kv(it + 2, buf);
    cp_commit();
  }

  float inv0 = 1.f / l0, inv1 = 1.f / l1;
#pragma unroll
  for (int j = 0; j < 8; j++) {
    int cw = j * 4 + qid;
    ofp[(size_t)(r0)     * (DH_ / 2) + cw] =
        pack_f16p(oacc[j][0] * inv0, oacc[j][1] * inv0);
    ofp[(size_t)(r0 + 8) * (DH_ / 2) + cw] =
        pack_f16p(oacc[j][2] * inv1, oacc[j][3] * inv1);
  }
}

// ---- input packing ----
__global__ void __launch_bounds__(256) pack_all(
    const float* __restrict__ y, const float* __restrict__ s,
    const float* __restrict__ b, const float* __restrict__ z,
    uint32_t* __restrict__ yfh, uint32_t* __restrict__ sfh,
    uint32_t* __restrict__ bfh, uint32_t* __restrict__ zfh) {
  const int which = blockIdx.y;
  const int i2 = blockIdx.x * 256 + threadIdx.x;
  const float* src; uint32_t* dst; int npair;
  switch (which) {
    case 0: src = y; dst = yfh; npair = M_ * DIN_ / 2; break;
    case 1: src = s; dst = sfh; npair = M_ * DH_ / 2; break;
    case 2: src = b; dst = bfh; npair = M_ * DH_ / 2; break;
    default: src = z; dst = zfh; npair = M_ * DH_ / 2; break;
  }
  if (i2 >= npair) return;
  float2 v = *(const float2*)(src + 2 * i2);
  dst[i2] = pack_f16p(v.x, v.y);
}

// ---- weight transpose ----
struct WEnt { const float* src; uint32_t* dst; int K; };
struct WTab { WEnt e[12]; };

__global__ void __launch_bounds__(256) transpose_w(const WTab tab) {
  WEnt e = tab.e[blockIdx.z];
  int n0 = blockIdx.x * 32, k0 = blockIdx.y * 32;
  if (k0 >= e.K) return;
  __shared__ float tl[32][33];
  int tx = threadIdx.x, ty = threadIdx.y;
#pragma unroll
  for (int i = 0; i < 32; i += 8)
    tl[ty + i][tx] = e.src[(size_t)(k0 + ty + i) * DH_ + n0 + tx];
  __syncthreads();
  if (tx < 16) {
#pragma unroll
    for (int i = 0; i < 32; i += 8) {
      int nn = ty + i;
      e.dst[(size_t)(n0 + nn) * (e.K / 2) + k0 / 2 + tx] =
          pack_f16p(tl[2 * tx][nn], tl[2 * tx + 1][nn]);
    }
  }
}

// ---- V transpose ----
__global__ void __launch_bounds__(256) transpose_v(const float* __restrict__ v,
                                                   uint32_t* __restrict__ vt) {
  int z = blockIdx.z, st = z >> 5, bh = z & 31, b = bh >> 4, h = bh & 15;
  int c0 = blockIdx.x * 32, k0 = blockIdx.y * 32;
  __shared__ float tl[32][33];
  int tx = threadIdx.x, ty = threadIdx.y;
  const float* src = v + (size_t)st * NTOK + (size_t)b * S_ * DH_ + h * HD_;
  uint32_t* dst = vt + (size_t)z * (HD_ * S_ / 2);
#pragma unroll
  for (int i = 0; i < 32; i += 8)
    tl[ty + i][tx] = src[(size_t)(k0 + ty + i) * DH_ + c0 + tx];
  __syncthreads();
  if (tx < 16) {
#pragma unroll
    for (int i = 0; i < 32; i += 8) {
      int cc = ty + i;
      dst[(size_t)(c0 + cc) * (S_ / 2) + k0 / 2 + tx] =
          pack_f16p(tl[2 * tx][cc], tl[2 * tx + 1][cc]);
    }
  }
}

// ---- residual chain ----
__global__ void __launch_bounds__(256) combine_kernel(
    const float* __restrict__ s, const float* __restrict__ b,
    const float* __restrict__ z, const float* __restrict__ ps,
    const float* __restrict__ pb, const float* __restrict__ pz,
    float* __restrict__ os, float* __restrict__ ob, float* __restrict__ oz) {
  size_t i = (size_t)blockIdx.x * 256 + threadIdx.x;
  if (i >= NTOK) return;
  float so = s[i] + ps[i];
  float bo = so + b[i] + pb[i];
  float zo = bo + z[i] + pz[i];
  os[i] = so; ob[i] = bo; oz[i] = zo;
}

// ===========================================================================
extern "C" void kernel_launch(void* const* d_in, const int* in_sizes, int n_in,
                              void* d_out, int out_size) {
  const float* y    = (const float*)d_in[0];
  const float* s    = (const float*)d_in[1];
  const float* b    = (const float*)d_in[2];
  const float* z    = (const float*)d_in[3];
  const float* ba0  = (const float*)d_in[4];
  const float* ba1  = (const float*)d_in[5];
  const float* ba2  = (const float*)d_in[6];
  const float* W[12] = {
      (const float*)d_in[7],  (const float*)d_in[9],  (const float*)d_in[11],
      (const float*)d_in[13], (const float*)d_in[15], (const float*)d_in[17],
      (const float*)d_in[19], (const float*)d_in[21],
      (const float*)d_in[23], (const float*)d_in[25], (const float*)d_in[27],
      (const float*)d_in[29]};
  const float* C[12] = {
      (const float*)d_in[8],  (const float*)d_in[10], (const float*)d_in[12],
      (const float*)d_in[14], (const float*)d_in[16], (const float*)d_in[18],
      (const float*)d_in[20], (const float*)d_in[22],
      (const float*)d_in[24], (const float*)d_in[26], (const float*)d_in[28],
      (const float*)d_in[30]};
  const int KW[12] = {DIN_, DIN_, DIN_, DH_, DH_, DH_, DH_, DH_,
                      DH_, DH_, DH_, DH_};

  float* out   = (float*)d_out;
  float* s_out = out;
  float* b_out = out + NTOK;
  float* z_out = out + 2 * NTOK;
  float* scb   = out + 3 * NTOK;

  uint32_t *gq, *gk, *gof, *gwtf, *gvth, *gyf, *gsf, *gbf, *gzf;
  float *gv, *gp;
  cudaGetSymbolAddress((void**)&gq, g_q);
  cudaGetSymbolAddress((void**)&gk, g_k);
  cudaGetSymbolAddress((void**)&gv, g_v);
  cudaGetSymbolAddress((void**)&gof, g_of);
  cudaGetSymbolAddress((void**)&gp, g_p);
  cudaGetSymbolAddress((void**)&gwtf, g_wtf);
  cudaGetSymbolAddress((void**)&gvth, g_vth);
  cudaGetSymbolAddress((void**)&gyf, g_yfh);
  cudaGetSymbolAddress((void**)&gsf, g_sfh);
  cudaGetSymbolAddress((void**)&gbf, g_bfh);
  cudaGetSymbolAddress((void**)&gzf, g_zfh);

  cudaFuncSetAttribute(fused_attn, cudaFuncAttributeMaxDynamicSharedMemorySize,
                       FUSED_SMEM);
  cudaFuncSetAttribute(proj_mixed, cudaFuncAttributeMaxDynamicSharedMemorySize,
                       GEMM_SMEM);

  // --- 1a: pack all inputs to f16 pairs ---
  pack_all<<<dim3(4096, 4), 256>>>(y, s, b, z, gyf, gsf, gbf, gzf);

  // --- 1b: transpose all weights to f16 pairs ---
  WTab wt{};
  for (int i = 0; i < 12; i++)
    wt.e[i] = {W[i], gwtf + (size_t)i * (DH_ * DH_ / 2), KW[i]};
  transpose_w<<<dim3(32, 32, 12), dim3(32, 8)>>>(wt);

  auto WTf = [&](int i) -> const uint32_t* {
    return gwtf + (size_t)i * (DH_ * DH_ / 2);
  };

  // --- 2: ALL 9 projection ops in ONE launch (heavy first) ---
  OpTable tab{};
  auto setp = [&](int idx, void* Cp, int Kw, int nt, int mode,
                  const uint32_t* A0, int w0,
                  const uint32_t* A1 = nullptr, int w1 = -1,
                  const uint32_t* A2 = nullptr, int w2 = -1) {
    Op& o = tab.op[idx];
    o.C = (float*)Cp; o.K = Kw; o.nt = nt; o.lda = Kw; o.ldb = Kw;
    o.ldc = (mode == 2) ? DH_ / 2 : DH_;
    o.mode = mode;
    o.t[0] = {A0, WTf(w0), C[w0]};
    if (nt > 1) o.t[1] = {A1, WTf(w1), C[w1]};
    if (nt > 2) o.t[2] = {A2, WTf(w2), C[w2]};
  };
  setp(0, gk + 1 * (NTOK / 2), DH_ / 2, 3, 2, gbf, 6, gsf, 4, gzf, 5);
  setp(1, gk + 0 * (NTOK / 2), DH_ / 2, 2, 2, gsf, 3, gbf, 4);
  setp(2, gk + 2 * (NTOK / 2), DH_ / 2, 2, 2, gzf, 7, gbf, 5);
  setp(3, gv + 0 * NTOK, DH_ / 2, 1, 0, gsf, 8);
  setp(4, gv + 1 * NTOK, DH_ / 2, 1, 0, gbf, 9);
  setp(5, gv + 2 * NTOK, DH_ / 2, 1, 0, gzf, 10);
  setp(6, gq + 0 * (NTOK / 2), DIN_ / 2, 1, 2, gyf, 0);
  setp(7, gq + 1 * (NTOK / 2), DIN_ / 2, 1, 2, gyf, 1);
  setp(8, gq + 2 * (NTOK / 2), DIN_ / 2, 1, 2, gyf, 2);
  proj_mixed<<<dim3(8, 16, 9), 256, GEMM_SMEM>>>(tab);

  // --- 3: V transpose ---
  transpose_v<<<dim3(2, 32, 96), dim3(32, 8)>>>(gv, gvth);

  // --- 4: fused attention (512 threads, 256 q-rows per CTA) ---
  fused_attn<<<dim3(S_ / 256, 96), 512, FUSED_SMEM>>>(gq, gk, gvth,
                                                      ba0, ba1, ba2, scb, gof);

  // --- 5: output projections (f16) ---
  OpTable to{};
  for (int i = 0; i < 3; i++) {
    Op& o = to.op[i];
    o.C = gp + (size_t)i * NTOK; o.K = DH_ / 2; o.nt = 1;
    o.lda = DH_ / 2; o.ldb = DH_ / 2; o.ldc = DH_;
    o.mode = 0;
    o.t[0] = {gof + (size_t)i * (NTOK / 2), WTf(11), C[11]};
  }
  proj_mixed<<<dim3(8, 16, 3), 256, GEMM_SMEM>>>(to);

  // --- 6: residual chain ---
  combine_kernel<<<(int)((NTOK + 255) / 256), 256>>>(
      s, b, z, gp + 0 * NTOK, gp + 1 * NTOK, gp + 2 * NTOK,
      s_out, b_out, z_out);
}